// round 12
// baseline (speedup 1.0000x reference)
#include <cuda_runtime.h>
#include <math.h>

#define NPTS 8192
#define BB   4
#define DD   128
#define KK   8
#define NB   (NPTS*BB)        // 32768
#define NR   (NB*KK)          // 262144

#define THREADS 512

#define WST2 136
#define AST2 68

#define OFF_WHI 0
#define OFF_WLO 8704
#define OFF_AHI 17408
#define OFF_ALO 26112
#define OFF_SB  34816
#define SMEM_WORDS 34944
#define SMEM_BYTES (SMEM_WORDS*4)

// ---------------- grid constants ----------------
#define GD   64
#define NC   (GD*GD*GD)       // 262144
#define CS   0.15625f
#define CINV 6.4f
#define CLO  (-5.0f)

// ---------------- scratch ----------------
__device__ float g_qf[BB*NPTS*DD];
__device__ float g_kf[BB*NPTS*DD];
__device__ float g_vf[BB*NPTS*DD];
__device__ float g_res[BB*NPTS*DD];
__device__ int   g_idx[BB*NPTS*KK];
__device__ float g_h [NR*DD];
__device__ float g_pe[NR*DD];
__device__ float g_u [NR*DD];
// grid scratch
__device__ int    g_cellcnt[BB*NC];
__device__ int    g_celloff[BB*NC];
__device__ int    g_cellcur[BB*NC];
__device__ int    g_pcell[NB];
__device__ float4 g_spts[NB];
__device__ int    g_sidx[NB];
__device__ int    g_stot[1024];

// ---------------- bf16 helpers ----------------
__device__ __forceinline__ unsigned bfpack(float lo_elem, float hi_elem) {
    unsigned r;
    asm("cvt.rn.bf16x2.f32 %0, %1, %2;" : "=r"(r) : "f"(hi_elem), "f"(lo_elem));
    return r;
}
__device__ __forceinline__ void bfsplit(float x0, float x1,
                                        unsigned& hp, unsigned& lp) {
    hp = bfpack(x0, x1);
    float h0 = __uint_as_float(hp << 16);
    float h1 = __uint_as_float(hp & 0xFFFF0000u);
    lp = bfpack(x0 - h0, x1 - h1);
}
__device__ __forceinline__ void mma_bf16(float* c, const unsigned* a,
                                         unsigned b0, unsigned b1) {
    asm volatile(
        "mma.sync.aligned.m16n8k16.row.col.f32.bf16.bf16.f32 "
        "{%0,%1,%2,%3}, {%4,%5,%6,%7}, {%8,%9}, {%0,%1,%2,%3};"
        : "+f"(c[0]), "+f"(c[1]), "+f"(c[2]), "+f"(c[3])
        : "r"(a[0]), "r"(a[1]), "r"(a[2]), "r"(a[3]), "r"(b0), "r"(b1));
}

// ============================================================================
// bf16-split MMA GEMM, persistent tile loop, 512 threads (R10 verbatim).
// ============================================================================
__global__ __launch_bounds__(THREADS, 1) void gemm_mma(
    const float* __restrict__ Aext, const float* __restrict__ W,
    const float* __restrict__ bias, const float* __restrict__ resid,
    float* __restrict__ outext, int ntiles, int mode)
{
    extern __shared__ unsigned smw[];
    unsigned* WhiP = smw + OFF_WHI;
    unsigned* WloP = smw + OFF_WLO;
    unsigned* AhiP = smw + OFF_AHI;
    unsigned* AloP = smw + OFF_ALO;
    float* sb = (float*)(smw + OFF_SB);

    const int tid = threadIdx.x;

    #pragma unroll
    for (int p = tid; p < 2048; p += THREADS) {
        int kk = p >> 5, nq = p & 31;
        const float4 L0 = *(const float4*)(W + (2*kk    )*128 + 4*nq);
        const float4 L1 = *(const float4*)(W + (2*kk + 1)*128 + 4*nq);
        uint4 h, l;
        bfsplit(L0.x, L1.x, h.x, l.x);
        bfsplit(L0.y, L1.y, h.y, l.y);
        bfsplit(L0.z, L1.z, h.z, l.z);
        bfsplit(L0.w, L1.w, h.w, l.w);
        *(uint4*)(WhiP + kk*WST2 + 4*nq) = h;
        *(uint4*)(WloP + kk*WST2 + 4*nq) = l;
    }
    if (tid < 128) sb[tid] = bias[tid];

    const float* Aptr = (mode == 3) ? (const float*)g_res :
                        (mode == 4) ? (const float*)g_h  :
                        (mode == 5) ? (const float*)g_u  : Aext;

    const int lane  = tid & 31;
    const int wid   = tid >> 5;
    const int warpM = (wid & 3) * 32;
    const int warpN = (wid >> 2) * 32;
    const int gid   = lane >> 2;
    const int tig   = lane & 3;

    for (int tile = blockIdx.x; tile < ntiles; tile += gridDim.x) {
        const int m0 = tile * 128;

        __syncthreads();
        #pragma unroll
        for (int i = tid; i < 4096; i += THREADS) {
            int m = i >> 5, cc = i & 31;
            int gm = m0 + m;
            int arow = (mode == 3) ? ((gm & 3) * NPTS + (gm >> 2)) : gm;
            float4 v = *(const float4*)(Aptr + (size_t)arow*DD + cc*4);
            uint2 h, l;
            bfsplit(v.x, v.y, h.x, l.x);
            bfsplit(v.z, v.w, h.y, l.y);
            *(uint2*)(AhiP + m*AST2 + 2*cc) = h;
            *(uint2*)(AloP + m*AST2 + 2*cc) = l;
        }
        __syncthreads();

        float acc[2][4][4];
        #pragma unroll
        for (int mt = 0; mt < 2; mt++)
            #pragma unroll
            for (int nt = 0; nt < 4; nt++)
                #pragma unroll
                for (int q = 0; q < 4; q++) acc[mt][nt][q] = 0.f;

        #pragma unroll 1
        for (int ks = 0; ks < 8; ++ks) {
            const int kk0 = ks * 8;
            unsigned ahi[2][4], alo[2][4];
            #pragma unroll
            for (int mt = 0; mt < 2; mt++) {
                const int r0 = warpM + mt*16 + gid;
                ahi[mt][0] = AhiP[(r0    )*AST2 + kk0 + tig];
                ahi[mt][1] = AhiP[(r0 + 8)*AST2 + kk0 + tig];
                ahi[mt][2] = AhiP[(r0    )*AST2 + kk0 + tig + 4];
                ahi[mt][3] = AhiP[(r0 + 8)*AST2 + kk0 + tig + 4];
                alo[mt][0] = AloP[(r0    )*AST2 + kk0 + tig];
                alo[mt][1] = AloP[(r0 + 8)*AST2 + kk0 + tig];
                alo[mt][2] = AloP[(r0    )*AST2 + kk0 + tig + 4];
                alo[mt][3] = AloP[(r0 + 8)*AST2 + kk0 + tig + 4];
            }
            #pragma unroll
            for (int nt = 0; nt < 4; nt++) {
                const int nc = warpN + nt*8 + gid;
                unsigned bh0 = WhiP[(kk0 + tig    )*WST2 + nc];
                unsigned bh1 = WhiP[(kk0 + tig + 4)*WST2 + nc];
                unsigned bl0 = WloP[(kk0 + tig    )*WST2 + nc];
                unsigned bl1 = WloP[(kk0 + tig + 4)*WST2 + nc];
                #pragma unroll
                for (int mt = 0; mt < 2; mt++) {
                    mma_bf16(acc[mt][nt], ahi[mt], bh0, bh1);
                    mma_bf16(acc[mt][nt], alo[mt], bh0, bh1);
                    mma_bf16(acc[mt][nt], ahi[mt], bl0, bl1);
                }
            }
        }

        #pragma unroll
        for (int mt = 0; mt < 2; mt++) {
            #pragma unroll
            for (int half = 0; half < 2; half++) {
                const int rl = warpM + mt*16 + gid + half*8;
                const int gm = m0 + rl;
                float* orow;
                const float* rrow = 0;
                if (mode == 0)      orow = g_qf + (size_t)((gm & 3)*NPTS + (gm >> 2)) * DD;
                else if (mode == 1) orow = g_kf + (size_t)((gm & 3)*NPTS + (gm >> 2)) * DD;
                else if (mode == 2) orow = g_vf + (size_t)((gm & 3)*NPTS + (gm >> 2)) * DD;
                else if (mode == 3) { orow = outext + (size_t)gm * DD; rrow = resid + (size_t)gm * DD; }
                else if (mode == 4) orow = g_pe + (size_t)gm * DD;
                else                orow = g_h  + (size_t)gm * DD;
                #pragma unroll
                for (int nt = 0; nt < 4; nt++) {
                    const int col = warpN + nt*8 + 2*tig;
                    float2 v;
                    v.x = acc[mt][nt][half*2    ] + sb[col];
                    v.y = acc[mt][nt][half*2 + 1] + sb[col + 1];
                    if (mode == 3) {
                        float2 rr = *(const float2*)(rrow + col);
                        v.x += rr.x; v.y += rr.y;
                    }
                    *(float2*)(orow + col) = v;
                }
            }
        }
    }
}

// ============================================================================
// Grid-based exact KNN
// ============================================================================
__global__ __launch_bounds__(1024, 1) void grid_clear_k()
{
    g_cellcnt[blockIdx.x * 1024 + threadIdx.x] = 0;
}

__global__ __launch_bounds__(256, 1) void grid_count_k(const float* __restrict__ pos)
{
    const int i = blockIdx.x * 256 + threadIdx.x;     // < NB
    const int b = i >> 13, n = i & (NPTS - 1);
    const float* p = pos + ((size_t)b * NPTS + n) * 3;
    float x = p[0], y = p[1], z = p[2];
    int cx = min(max((int)((x - CLO) * CINV), 0), GD - 1);
    int cy = min(max((int)((y - CLO) * CINV), 0), GD - 1);
    int cz = min(max((int)((z - CLO) * CINV), 0), GD - 1);
    int cell = b * NC + (cz * GD + cy) * GD + cx;
    g_pcell[i] = cell;
    atomicAdd(&g_cellcnt[cell], 1);
}

__global__ __launch_bounds__(1024, 1) void grid_scan1_k()
{
    __shared__ int sm[1024];
    const int tid = threadIdx.x;
    const int gid = blockIdx.x * 1024 + tid;
    int v = g_cellcnt[gid];
    sm[tid] = v;
    __syncthreads();
    for (int ofs = 1; ofs < 1024; ofs <<= 1) {
        int t = (tid >= ofs) ? sm[tid - ofs] : 0;
        __syncthreads();
        sm[tid] += t;
        __syncthreads();
    }
    g_celloff[gid] = sm[tid] - v;           // exclusive within block
    if (tid == 1023) g_stot[blockIdx.x] = sm[tid];
}

__global__ __launch_bounds__(1024, 1) void grid_scan2_k()
{
    __shared__ int sm[1024];
    const int tid = threadIdx.x;
    int v = g_stot[tid];
    sm[tid] = v;
    __syncthreads();
    for (int ofs = 1; ofs < 1024; ofs <<= 1) {
        int t = (tid >= ofs) ? sm[tid - ofs] : 0;
        __syncthreads();
        sm[tid] += t;
        __syncthreads();
    }
    g_stot[tid] = sm[tid] - v;              // exclusive block bases
}

__global__ __launch_bounds__(1024, 1) void grid_scan3_k()
{
    const int gid = blockIdx.x * 1024 + threadIdx.x;
    int o = g_celloff[gid] + g_stot[blockIdx.x];
    g_celloff[gid] = o;
    g_cellcur[gid] = o;
}

__global__ __launch_bounds__(256, 1) void grid_scatter_k(const float* __restrict__ pos)
{
    const int i = blockIdx.x * 256 + threadIdx.x;     // < NB
    const int b = i >> 13, n = i & (NPTS - 1);
    const float* p = pos + ((size_t)b * NPTS + n) * 3;
    float x = p[0], y = p[1], z = p[2];
    int cell = g_pcell[i];
    int s = atomicAdd(&g_cellcur[cell], 1);
    g_spts[s] = make_float4(x, y, z, fmaf(z, z, fmaf(y, y, x*x)));
    g_sidx[s] = n;
}

// per-query ring-expansion search; thread j handles sorted slot j (batch = j>>13)
__global__ __launch_bounds__(128, 1) void grid_query_k()
{
    const int j = blockIdx.x * 128 + threadIdx.x;     // < NB
    const int b = j >> 13;
    const float4 q = g_spts[j];
    const int qidx = g_sidx[j];
    const float nx = -2.f*q.x, ny = -2.f*q.y, nz = -2.f*q.z;
    const float qsq = q.w;
    const int cx = min(max((int)((q.x - CLO) * CINV), 0), GD - 1);
    const int cy = min(max((int)((q.y - CLO) * CINV), 0), GD - 1);
    const int cz = min(max((int)((q.z - CLO) * CINV), 0), GD - 1);
    const int cb = b * NC;

    float bd[8]; int bi[8];
    #pragma unroll
    for (int k = 0; k < 8; k++) { bd[k] = 1e30f; bi[k] = 0x7fffffff; }

    for (int r = 1; r <= GD; ++r) {
        const int zlo = max(cz - r, 0), zhi = min(cz + r, GD - 1);
        const int ylo = max(cy - r, 0), yhi = min(cy + r, GD - 1);
        const int xlo = max(cx - r, 0), xhi = min(cx + r, GD - 1);

        for (int z = zlo; z <= zhi; ++z) {
            const bool zface = (z == cz - r) || (z == cz + r);
            for (int y = ylo; y <= yhi; ++y) {
                const bool face = (r == 1) || zface || (y == cy - r) || (y == cy + r);
                const int rowb = cb + (z * GD + y) * GD;
                int beg, end;
                for (int seg = 0; seg < 2; ++seg) {
                    if (face) {
                        if (seg) break;
                        beg = g_celloff[rowb + xlo];
                        end = g_celloff[rowb + xhi] + g_cellcnt[rowb + xhi];
                    } else {
                        int xs = seg ? (cx + r) : (cx - r);
                        if (xs < 0 || xs >= GD) continue;
                        beg = g_celloff[rowb + xs];
                        end = beg + g_cellcnt[rowb + xs];
                    }
                    for (int i = beg; i < end; ++i) {
                        float4 c = g_spts[i];
                        float sv = fmaf(nx, c.x, fmaf(ny, c.y, fmaf(nz, c.z, c.w)));
                        int ci = g_sidx[i];
                        if (sv < bd[7] || (sv == bd[7] && ci < bi[7])) {
                            bd[7] = sv; bi[7] = ci;
                            #pragma unroll
                            for (int k = 7; k > 0; --k) {
                                if (bd[k] < bd[k-1] ||
                                    (bd[k] == bd[k-1] && bi[k] < bi[k-1])) {
                                    float td = bd[k]; bd[k] = bd[k-1]; bd[k-1] = td;
                                    int   ti = bi[k]; bi[k] = bi[k-1]; bi[k-1] = ti;
                                }
                            }
                        }
                    }
                }
            }
        }

        // termination: full coverage, or 8 found with safe face margin
        bool cover = (zlo == 0 && zhi == GD-1 && ylo == 0 && yhi == GD-1 &&
                      xlo == 0 && xhi == GD-1);
        float fxl = (cx - r > 0)      ? (q.x - (CLO + (cx - r) * CS))     : 1e30f;
        float fxh = (cx + r < GD - 1) ? ((CLO + (cx + r + 1) * CS) - q.x) : 1e30f;
        float fyl = (cy - r > 0)      ? (q.y - (CLO + (cy - r) * CS))     : 1e30f;
        float fyh = (cy + r < GD - 1) ? ((CLO + (cy + r + 1) * CS) - q.y) : 1e30f;
        float fzl = (cz - r > 0)      ? (q.z - (CLO + (cz - r) * CS))     : 1e30f;
        float fzh = (cz + r < GD - 1) ? ((CLO + (cz + r + 1) * CS) - q.z) : 1e30f;
        float df = fminf(fminf(fxl, fxh), fminf(fminf(fyl, fyh), fminf(fzl, fzh)));
        if (cover || (bd[7] < 1e29f && qsq + bd[7] + 1e-3f <= df * df)) break;
    }

    int* op = g_idx + ((size_t)b * NPTS + qidx) * KK;
    #pragma unroll
    for (int k = 0; k < 8; k++) op[k] = bi[k];
}

// ============================================================================
// build h (float4) — R10 verbatim
// ============================================================================
__global__ __launch_bounds__(256, 1) void buildh_k(
    const float* __restrict__ pos,
    const float* __restrict__ Wp1, const float* __restrict__ bp1)
{
    const int gid = blockIdx.x * 256 + threadIdx.x;   // < NR*32
    const int r = gid >> 5, d0 = (gid & 31) * 4;
    const int g = r >> 3;
    const int b = g >> 13, n = g & (NPTS - 1);
    const int id = g_idx[r];
    const float* pb = pos + (size_t)b * NPTS * 3;
    const float rx = pb[n*3+0] - pb[id*3+0];
    const float ry = pb[n*3+1] - pb[id*3+1];
    const float rz = pb[n*3+2] - pb[id*3+2];
    const float4 wx = *(const float4*)(Wp1 + d0);
    const float4 wy = *(const float4*)(Wp1 + 128 + d0);
    const float4 wz = *(const float4*)(Wp1 + 256 + d0);
    const float4 bb = *(const float4*)(bp1 + d0);
    float4 o;
    {
        float z = fmaf(rz, wz.x, fmaf(ry, wy.x, fmaf(rx, wx.x, bb.x)));
        o.x = 0.5f * z * (1.f + erff(z * 0.70710678118654752f));
    }
    {
        float z = fmaf(rz, wz.y, fmaf(ry, wy.y, fmaf(rx, wx.y, bb.y)));
        o.y = 0.5f * z * (1.f + erff(z * 0.70710678118654752f));
    }
    {
        float z = fmaf(rz, wz.z, fmaf(ry, wy.z, fmaf(rx, wx.z, bb.z)));
        o.z = 0.5f * z * (1.f + erff(z * 0.70710678118654752f));
    }
    {
        float z = fmaf(rz, wz.w, fmaf(ry, wy.w, fmaf(rx, wx.w, bb.w)));
        o.w = 0.5f * z * (1.f + erff(z * 0.70710678118654752f));
    }
    *(float4*)(g_h + (size_t)r*DD + d0) = o;
}

// ============================================================================
// build u (float4) — R10 verbatim
// ============================================================================
__global__ __launch_bounds__(256, 1) void buildu_k()
{
    const int gid = blockIdx.x * 256 + threadIdx.x;   // < NR*32
    const int r = gid >> 5, seg = (gid & 31) * 4;
    const int g = r >> 3;
    const int id = g_idx[r];
    const int b = g >> 13;
    float4 qv = *(const float4*)(g_qf + (size_t)g * DD + seg);
    float4 kv = *(const float4*)(g_kf + ((size_t)b * NPTS + id) * DD + seg);
    float4 pe = *(const float4*)(g_pe + (size_t)r * DD + seg);
    float4 u;
    u.x = qv.x - kv.x + pe.x; u.y = qv.y - kv.y + pe.y;
    u.z = qv.z - kv.z + pe.z; u.w = qv.w - kv.w + pe.w;
    *(float4*)(g_u + (size_t)r * DD + seg) = u;
}

// ============================================================================
// finish — R10 verbatim
// ============================================================================
__global__ __launch_bounds__(256, 1) void finish_k()
{
    __shared__ float rA[2][32];
    __shared__ float rB[2][32];

    const int tid  = threadIdx.x;
    const int grp  = tid >> 7;
    const int d    = tid & 127;
    const int lane = tid & 31;
    const int wsub = (tid >> 5) & 3;
    const int g    = blockIdx.x * 2 + grp;
    const int b    = g >> 13;
    const float scale = 0.08838834764831845f;   // 1/sqrt(128)

    float a[8];
    #pragma unroll
    for (int k = 0; k < 8; ++k)
        a[k] = g_h[((size_t)g*8 + k) * DD + d] * scale;

    float red[8];
    #pragma unroll
    for (int k = 0; k < 8; ++k) red[k] = a[k];
    #pragma unroll
    for (int off = 16; off > 0; off >>= 1)
        #pragma unroll
        for (int k = 0; k < 8; ++k)
            red[k] = fmaxf(red[k], __shfl_xor_sync(0xffffffffu, red[k], off));
    if (lane == 0) {
        #pragma unroll
        for (int k = 0; k < 8; ++k) rA[grp][wsub*8 + k] = red[k];
    }
    __syncthreads();

    float e[8];
    #pragma unroll
    for (int k = 0; k < 8; ++k) {
        float bm = fmaxf(fmaxf(rA[grp][k], rA[grp][8+k]),
                         fmaxf(rA[grp][16+k], rA[grp][24+k]));
        e[k] = __expf(a[k] - bm);
        red[k] = e[k];
    }
    #pragma unroll
    for (int off = 16; off > 0; off >>= 1)
        #pragma unroll
        for (int k = 0; k < 8; ++k)
            red[k] += __shfl_xor_sync(0xffffffffu, red[k], off);
    if (lane == 0) {
        #pragma unroll
        for (int k = 0; k < 8; ++k) rB[grp][wsub*8 + k] = red[k];
    }
    __syncthreads();

    float rsum = 0.f;
    #pragma unroll
    for (int k = 0; k < 8; ++k) {
        float tot = (rB[grp][k] + rB[grp][8+k]) + (rB[grp][16+k] + rB[grp][24+k]);
        float smx = e[k] / tot;
        int id = g_idx[(size_t)g*8 + k];
        float v  = g_vf[((size_t)b * NPTS + id) * DD + d];
        float pe = g_pe[((size_t)g*8 + k) * DD + d];
        rsum = fmaf(smx, v + pe, rsum);
    }
    g_res[(size_t)g * DD + d] = rsum;
}

// ============================================================================
// host launch
// ============================================================================
extern "C" void kernel_launch(void* const* d_in, const int* in_sizes, int n_in,
                              void* d_out, int out_size)
{
    const float* query = (const float*)d_in[0];
    const float* pos   = (const float*)d_in[1];
    const float* Wq  = (const float*)d_in[2];  const float* bq  = (const float*)d_in[3];
    const float* Wk  = (const float*)d_in[4];  const float* bk  = (const float*)d_in[5];
    const float* Wv  = (const float*)d_in[6];  const float* bv  = (const float*)d_in[7];
    const float* Wp1 = (const float*)d_in[8];  const float* bp1 = (const float*)d_in[9];
    const float* Wp2 = (const float*)d_in[10]; const float* bp2 = (const float*)d_in[11];
    const float* Wg  = (const float*)d_in[12]; const float* bg  = (const float*)d_in[13];
    const float* Wo  = (const float*)d_in[14]; const float* bo  = (const float*)d_in[15];
    float* out = (float*)d_out;

    cudaFuncSetAttribute(gemm_mma, cudaFuncAttributeMaxDynamicSharedMemorySize, SMEM_BYTES);

    int dev = 0, sms = 148;
    cudaGetDevice(&dev);
    cudaDeviceGetAttribute(&sms, cudaDevAttrMultiProcessorCount, dev);

    const int NT_NB = NB/128;   // 256
    const int NT_NR = NR/128;   // 2048
    const int gNB = (NT_NB < sms) ? NT_NB : sms;
    const int gNR = sms;

    // ---- grid KNN pipeline ----
    grid_clear_k<<<1024, 1024>>>();
    grid_count_k<<<NB/256, 256>>>(pos);
    grid_scan1_k<<<1024, 1024>>>();
    grid_scan2_k<<<1, 1024>>>();
    grid_scan3_k<<<1024, 1024>>>();
    grid_scatter_k<<<NB/256, 256>>>(pos);
    grid_query_k<<<NB/128, 128>>>();

    // QKV projections -> g_qf/g_kf/g_vf in [B,N,D]
    gemm_mma<<<gNB, THREADS, SMEM_BYTES>>>(query, Wq, bq, 0, 0, NT_NB, 0);
    gemm_mma<<<gNB, THREADS, SMEM_BYTES>>>(query, Wk, bk, 0, 0, NT_NB, 1);
    gemm_mma<<<gNB, THREADS, SMEM_BYTES>>>(query, Wv, bv, 0, 0, NT_NB, 2);

    // h = gelu(lin1(rel))          [NR,128]
    buildh_k<<<NR*32/256, 256>>>(pos, Wp1, bp1);

    // pe = h @ Wp2 + bp2           [NR,128]
    gemm_mma<<<gNR, THREADS, SMEM_BYTES>>>(0, Wp2, bp2, 0, 0, NT_NR, 4);

    // u = q - k_knn + pe           [NR,128]
    buildu_k<<<NR*32/256, 256>>>();

    // a = u @ Wg + bg              [NR,128]  (into g_h)
    gemm_mma<<<gNR, THREADS, SMEM_BYTES>>>(0, Wg, bg, 0, 0, NT_NR, 5);

    // softmax over d + weighted sum over k -> g_res [B,N,D]
    finish_k<<<NB/2, 256>>>();

    // out = res@Wo + bo + query    [N,B,D]
    gemm_mma<<<gNB, THREADS, SMEM_BYTES>>>(query, Wo, bo, query, out, NT_NB, 3);
}

// round 13
// speedup vs baseline: 3.1014x; 3.1014x over previous
#include <cuda_runtime.h>
#include <math.h>

#define NPTS 8192
#define BB   4
#define DD   128
#define KK   8
#define NB   (NPTS*BB)        // 32768
#define NR   (NB*KK)          // 262144

#define THREADS 512

#define WST2 136
#define AST2 68

#define OFF_WHI 0
#define OFF_WLO 8704
#define OFF_AHI 17408
#define OFF_ALO 26112
#define OFF_SB  34816
#define SMEM_WORDS 34944
#define SMEM_BYTES (SMEM_WORDS*4)

// knn smem layout (bytes)
#define STK      16
#define KOFF_CAND 0            // float4[1032] = 16512
#define KOFF_STK  16512        // int2[16][256] = 32768
#define KOFF_SD   49280        // float[2048] = 8192
#define KOFF_SI   57472        // int[2048] = 8192
#define KNN_SMEM  65664

// ---------------- scratch ----------------
__device__ float g_qf[BB*NPTS*DD];
__device__ float g_kf[BB*NPTS*DD];
__device__ float g_vf[BB*NPTS*DD];
__device__ float g_res[BB*NPTS*DD];
__device__ int   g_idx[BB*NPTS*KK];
__device__ float g_h [NR*DD];
__device__ float g_pe[NR*DD];
__device__ float g_u [NR*DD];

// ---------------- bf16 helpers ----------------
__device__ __forceinline__ unsigned bfpack(float lo_elem, float hi_elem) {
    unsigned r;
    asm("cvt.rn.bf16x2.f32 %0, %1, %2;" : "=r"(r) : "f"(hi_elem), "f"(lo_elem));
    return r;
}
__device__ __forceinline__ void bfsplit(float x0, float x1,
                                        unsigned& hp, unsigned& lp) {
    hp = bfpack(x0, x1);
    float h0 = __uint_as_float(hp << 16);
    float h1 = __uint_as_float(hp & 0xFFFF0000u);
    lp = bfpack(x0 - h0, x1 - h1);
}
__device__ __forceinline__ void mma_bf16(float* c, const unsigned* a,
                                         unsigned b0, unsigned b1) {
    asm volatile(
        "mma.sync.aligned.m16n8k16.row.col.f32.bf16.bf16.f32 "
        "{%0,%1,%2,%3}, {%4,%5,%6,%7}, {%8,%9}, {%0,%1,%2,%3};"
        : "+f"(c[0]), "+f"(c[1]), "+f"(c[2]), "+f"(c[3])
        : "r"(a[0]), "r"(a[1]), "r"(a[2]), "r"(a[3]), "r"(b0), "r"(b1));
}

// ============================================================================
// bf16-split MMA GEMM, persistent tile loop, 512 threads (R10 + tile0 param).
// ============================================================================
__global__ __launch_bounds__(THREADS, 1) void gemm_mma(
    const float* __restrict__ Aext, const float* __restrict__ W,
    const float* __restrict__ bias, const float* __restrict__ resid,
    float* __restrict__ outext, int tile0, int ntiles, int mode)
{
    extern __shared__ unsigned smw[];
    unsigned* WhiP = smw + OFF_WHI;
    unsigned* WloP = smw + OFF_WLO;
    unsigned* AhiP = smw + OFF_AHI;
    unsigned* AloP = smw + OFF_ALO;
    float* sb = (float*)(smw + OFF_SB);

    const int tid = threadIdx.x;

    #pragma unroll
    for (int p = tid; p < 2048; p += THREADS) {
        int kk = p >> 5, nq = p & 31;
        const float4 L0 = *(const float4*)(W + (2*kk    )*128 + 4*nq);
        const float4 L1 = *(const float4*)(W + (2*kk + 1)*128 + 4*nq);
        uint4 h, l;
        bfsplit(L0.x, L1.x, h.x, l.x);
        bfsplit(L0.y, L1.y, h.y, l.y);
        bfsplit(L0.z, L1.z, h.z, l.z);
        bfsplit(L0.w, L1.w, h.w, l.w);
        *(uint4*)(WhiP + kk*WST2 + 4*nq) = h;
        *(uint4*)(WloP + kk*WST2 + 4*nq) = l;
    }
    if (tid < 128) sb[tid] = bias[tid];

    const float* Aptr = (mode == 3) ? (const float*)g_res :
                        (mode == 4) ? (const float*)g_h  :
                        (mode == 5) ? (const float*)g_u  : Aext;

    const int lane  = tid & 31;
    const int wid   = tid >> 5;
    const int warpM = (wid & 3) * 32;
    const int warpN = (wid >> 2) * 32;
    const int gid   = lane >> 2;
    const int tig   = lane & 3;

    for (int tile = blockIdx.x + tile0; tile < tile0 + ntiles; tile += gridDim.x) {
        const int m0 = tile * 128;

        __syncthreads();
        #pragma unroll
        for (int i = tid; i < 4096; i += THREADS) {
            int m = i >> 5, cc = i & 31;
            int gm = m0 + m;
            int arow = (mode == 3) ? ((gm & 3) * NPTS + (gm >> 2)) : gm;
            float4 v = *(const float4*)(Aptr + (size_t)arow*DD + cc*4);
            uint2 h, l;
            bfsplit(v.x, v.y, h.x, l.x);
            bfsplit(v.z, v.w, h.y, l.y);
            *(uint2*)(AhiP + m*AST2 + 2*cc) = h;
            *(uint2*)(AloP + m*AST2 + 2*cc) = l;
        }
        __syncthreads();

        float acc[2][4][4];
        #pragma unroll
        for (int mt = 0; mt < 2; mt++)
            #pragma unroll
            for (int nt = 0; nt < 4; nt++)
                #pragma unroll
                for (int q = 0; q < 4; q++) acc[mt][nt][q] = 0.f;

        #pragma unroll 1
        for (int ks = 0; ks < 8; ++ks) {
            const int kk0 = ks * 8;
            unsigned ahi[2][4], alo[2][4];
            #pragma unroll
            for (int mt = 0; mt < 2; mt++) {
                const int r0 = warpM + mt*16 + gid;
                ahi[mt][0] = AhiP[(r0    )*AST2 + kk0 + tig];
                ahi[mt][1] = AhiP[(r0 + 8)*AST2 + kk0 + tig];
                ahi[mt][2] = AhiP[(r0    )*AST2 + kk0 + tig + 4];
                ahi[mt][3] = AhiP[(r0 + 8)*AST2 + kk0 + tig + 4];
                alo[mt][0] = AloP[(r0    )*AST2 + kk0 + tig];
                alo[mt][1] = AloP[(r0 + 8)*AST2 + kk0 + tig];
                alo[mt][2] = AloP[(r0    )*AST2 + kk0 + tig + 4];
                alo[mt][3] = AloP[(r0 + 8)*AST2 + kk0 + tig + 4];
            }
            #pragma unroll
            for (int nt = 0; nt < 4; nt++) {
                const int nc = warpN + nt*8 + gid;
                unsigned bh0 = WhiP[(kk0 + tig    )*WST2 + nc];
                unsigned bh1 = WhiP[(kk0 + tig + 4)*WST2 + nc];
                unsigned bl0 = WloP[(kk0 + tig    )*WST2 + nc];
                unsigned bl1 = WloP[(kk0 + tig + 4)*WST2 + nc];
                #pragma unroll
                for (int mt = 0; mt < 2; mt++) {
                    mma_bf16(acc[mt][nt], ahi[mt], bh0, bh1);
                    mma_bf16(acc[mt][nt], alo[mt], bh0, bh1);
                    mma_bf16(acc[mt][nt], ahi[mt], bl0, bl1);
                }
            }
        }

        #pragma unroll
        for (int mt = 0; mt < 2; mt++) {
            #pragma unroll
            for (int half = 0; half < 2; half++) {
                const int rl = warpM + mt*16 + gid + half*8;
                const int gm = m0 + rl;
                float* orow;
                const float* rrow = 0;
                if (mode == 0)      orow = g_qf + (size_t)((gm & 3)*NPTS + (gm >> 2)) * DD;
                else if (mode == 1) orow = g_kf + (size_t)((gm & 3)*NPTS + (gm >> 2)) * DD;
                else if (mode == 2) orow = g_vf + (size_t)((gm & 3)*NPTS + (gm >> 2)) * DD;
                else if (mode == 3) { orow = outext + (size_t)gm * DD; rrow = resid + (size_t)gm * DD; }
                else if (mode == 4) orow = g_pe + (size_t)gm * DD;
                else                orow = g_h  + (size_t)gm * DD;
                #pragma unroll
                for (int nt = 0; nt < 4; nt++) {
                    const int col = warpN + nt*8 + 2*tig;
                    float2 v;
                    v.x = acc[mt][nt][half*2    ] + sb[col];
                    v.y = acc[mt][nt][half*2 + 1] + sb[col + 1];
                    if (mode == 3) {
                        float2 rr = *(const float2*)(rrow + col);
                        v.x += rr.x; v.y += rr.y;
                    }
                    *(float2*)(orow + col) = v;
                }
            }
        }
    }
}

// ============================================================================
// KNN v6: 8-way split, shift trick, PREDICATED STACK FILTER.
// Hot loop is branch-free: unconditional STS.64 to stack slot + conditional
// sp increment. Stack drained (exact R10 insert chain) at subchunk
// boundaries — rare after warm-up. Selection semantics identical to R10.
// ============================================================================
#define KNN_DRAIN()                                                        \
    do {                                                                   \
        for (int ii = 0; ii < sp; ++ii) {                                  \
            int2 e = stk[(ii << 8) + t];                                   \
            float dv = __int_as_float(e.x);                                \
            if (dv < bd[7]) {                                              \
                bd[7] = dv; bi[7] = e.y;                                   \
                _Pragma("unroll")                                          \
                for (int r = 7; r > 0; --r) {                              \
                    if (bd[r] < bd[r-1]) {                                 \
                        float td = bd[r]; bd[r] = bd[r-1]; bd[r-1] = td;   \
                        int   ti = bi[r]; bi[r] = bi[r-1]; bi[r-1] = ti;   \
                    }                                                      \
                }                                                          \
            }                                                              \
        }                                                                  \
        sp = 0;                                                            \
        bd7 = bd[7];                                                       \
    } while (0)

__global__ __launch_bounds__(256, 1) void knn_k(const float* __restrict__ pos)
{
    extern __shared__ char ksm[];
    float4* cand = (float4*)(ksm + KOFF_CAND);   // [1032], stride 129/chunk
    int2*   stk  = (int2*)(ksm + KOFF_STK);      // [STK][256] lane-major
    float*  sd   = (float*)(ksm + KOFF_SD);      // [256*8]
    int*    si   = (int*)(ksm + KOFF_SI);        // [256*8]

    const int b = blockIdx.y;
    const int t = threadIdx.x;
    const int q = blockIdx.x * 32 + (t >> 3);
    const int s = t & 7;
    const float* pb = pos + (size_t)b * NPTS * 3;

    const float qx = pb[q*3], qy = pb[q*3+1], qz = pb[q*3+2];
    const float nx = -2.f*qx, ny = -2.f*qy, nz = -2.f*qz;

    float bd[8]; int bi[8];
    #pragma unroll
    for (int k = 0; k < 8; k++) { bd[k] = 1e30f; bi[k] = 0x7fffffff; }
    float bd7 = 1e30f;
    int sp = 0;

    const int base = s * 129;
    const int idxb = s * 128;

    for (int t0 = 0; t0 < NPTS; t0 += 1024) {
        __syncthreads();
        #pragma unroll
        for (int i = t; i < 1024; i += 256) {
            float x = pb[(t0+i)*3], y = pb[(t0+i)*3+1], z = pb[(t0+i)*3+2];
            cand[i + (i >> 7)] = make_float4(x, y, z, fmaf(z, z, fmaf(y, y, x*x)));
        }
        __syncthreads();

        #pragma unroll 1
        for (int sub = 0; sub < 16; ++sub) {
            const int mbase = sub * 8;
            const int ibase = t0 + idxb + mbase;
            #pragma unroll
            for (int mm = 0; mm < 8; ++mm) {
                float4 c = cand[base + mbase + mm];
                float sv = fmaf(nx, c.x, fmaf(ny, c.y, fmaf(nz, c.z, c.w)));
                // branch-free push: always store, conditionally advance
                stk[((sp & (STK-1)) << 8) + t] =
                    make_int2(__float_as_int(sv), ibase + mm);
                sp += (sv < bd7) ? 1 : 0;
            }
            if (sp > STK - 8) {
                KNN_DRAIN();
            }
        }
    }
    KNN_DRAIN();

    #pragma unroll
    for (int k = 0; k < 8; k++) { sd[t*8+k] = bd[k]; si[t*8+k] = bi[k]; }
    __syncthreads();

    if (s == 0) {
        int p[8] = {0,0,0,0,0,0,0,0};
        int* op = g_idx + ((size_t)b * NPTS + q) * KK;
        #pragma unroll
        for (int o = 0; o < 8; ++o) {
            float bdv = 1e38f; int biv = 0x7fffffff; int bl = 0;
            #pragma unroll
            for (int l = 0; l < 8; ++l) {
                float dv = sd[(t+l)*8 + p[l]];
                int   iv = si[(t+l)*8 + p[l]];
                if (dv < bdv || (dv == bdv && iv < biv)) { bdv = dv; biv = iv; bl = l; }
            }
            op[o] = biv;
            p[bl]++;
        }
    }
}

// ============================================================================
// build h (float4) — R10 verbatim
// ============================================================================
__global__ __launch_bounds__(256, 1) void buildh_k(
    const float* __restrict__ pos,
    const float* __restrict__ Wp1, const float* __restrict__ bp1)
{
    const int gid = blockIdx.x * 256 + threadIdx.x;   // < NR*32
    const int r = gid >> 5, d0 = (gid & 31) * 4;
    const int g = r >> 3;
    const int b = g >> 13, n = g & (NPTS - 1);
    const int id = g_idx[r];
    const float* pb = pos + (size_t)b * NPTS * 3;
    const float rx = pb[n*3+0] - pb[id*3+0];
    const float ry = pb[n*3+1] - pb[id*3+1];
    const float rz = pb[n*3+2] - pb[id*3+2];
    const float4 wx = *(const float4*)(Wp1 + d0);
    const float4 wy = *(const float4*)(Wp1 + 128 + d0);
    const float4 wz = *(const float4*)(Wp1 + 256 + d0);
    const float4 bb = *(const float4*)(bp1 + d0);
    float4 o;
    {
        float z = fmaf(rz, wz.x, fmaf(ry, wy.x, fmaf(rx, wx.x, bb.x)));
        o.x = 0.5f * z * (1.f + erff(z * 0.70710678118654752f));
    }
    {
        float z = fmaf(rz, wz.y, fmaf(ry, wy.y, fmaf(rx, wx.y, bb.y)));
        o.y = 0.5f * z * (1.f + erff(z * 0.70710678118654752f));
    }
    {
        float z = fmaf(rz, wz.z, fmaf(ry, wy.z, fmaf(rx, wx.z, bb.z)));
        o.z = 0.5f * z * (1.f + erff(z * 0.70710678118654752f));
    }
    {
        float z = fmaf(rz, wz.w, fmaf(ry, wy.w, fmaf(rx, wx.w, bb.w)));
        o.w = 0.5f * z * (1.f + erff(z * 0.70710678118654752f));
    }
    *(float4*)(g_h + (size_t)r*DD + d0) = o;
}

// ============================================================================
// build u (float4) — R10 verbatim
// ============================================================================
__global__ __launch_bounds__(256, 1) void buildu_k()
{
    const int gid = blockIdx.x * 256 + threadIdx.x;   // < NR*32
    const int r = gid >> 5, seg = (gid & 31) * 4;
    const int g = r >> 3;
    const int id = g_idx[r];
    const int b = g >> 13;
    float4 qv = *(const float4*)(g_qf + (size_t)g * DD + seg);
    float4 kv = *(const float4*)(g_kf + ((size_t)b * NPTS + id) * DD + seg);
    float4 pe = *(const float4*)(g_pe + (size_t)r * DD + seg);
    float4 u;
    u.x = qv.x - kv.x + pe.x; u.y = qv.y - kv.y + pe.y;
    u.z = qv.z - kv.z + pe.z; u.w = qv.w - kv.w + pe.w;
    *(float4*)(g_u + (size_t)r * DD + seg) = u;
}

// ============================================================================
// finish — R10 verbatim
// ============================================================================
__global__ __launch_bounds__(256, 1) void finish_k()
{
    __shared__ float rA[2][32];
    __shared__ float rB[2][32];

    const int tid  = threadIdx.x;
    const int grp  = tid >> 7;
    const int d    = tid & 127;
    const int lane = tid & 31;
    const int wsub = (tid >> 5) & 3;
    const int g    = blockIdx.x * 2 + grp;
    const int b    = g >> 13;
    const float scale = 0.08838834764831845f;   // 1/sqrt(128)

    float a[8];
    #pragma unroll
    for (int k = 0; k < 8; ++k)
        a[k] = g_h[((size_t)g*8 + k) * DD + d] * scale;

    float red[8];
    #pragma unroll
    for (int k = 0; k < 8; ++k) red[k] = a[k];
    #pragma unroll
    for (int off = 16; off > 0; off >>= 1)
        #pragma unroll
        for (int k = 0; k < 8; ++k)
            red[k] = fmaxf(red[k], __shfl_xor_sync(0xffffffffu, red[k], off));
    if (lane == 0) {
        #pragma unroll
        for (int k = 0; k < 8; ++k) rA[grp][wsub*8 + k] = red[k];
    }
    __syncthreads();

    float e[8];
    #pragma unroll
    for (int k = 0; k < 8; ++k) {
        float bm = fmaxf(fmaxf(rA[grp][k], rA[grp][8+k]),
                         fmaxf(rA[grp][16+k], rA[grp][24+k]));
        e[k] = __expf(a[k] - bm);
        red[k] = e[k];
    }
    #pragma unroll
    for (int off = 16; off > 0; off >>= 1)
        #pragma unroll
        for (int k = 0; k < 8; ++k)
            red[k] += __shfl_xor_sync(0xffffffffu, red[k], off);
    if (lane == 0) {
        #pragma unroll
        for (int k = 0; k < 8; ++k) rB[grp][wsub*8 + k] = red[k];
    }
    __syncthreads();

    float rsum = 0.f;
    #pragma unroll
    for (int k = 0; k < 8; ++k) {
        float tot = (rB[grp][k] + rB[grp][8+k]) + (rB[grp][16+k] + rB[grp][24+k]);
        float smx = e[k] / tot;
        int id = g_idx[(size_t)g*8 + k];
        float v  = g_vf[((size_t)b * NPTS + id) * DD + d];
        float pe = g_pe[((size_t)g*8 + k) * DD + d];
        rsum = fmaf(smx, v + pe, rsum);
    }
    g_res[(size_t)g * DD + d] = rsum;
}

// ============================================================================
// host launch — ordered so launch #6 (ncu -s 5 -c 1) is knn_k
// ============================================================================
extern "C" void kernel_launch(void* const* d_in, const int* in_sizes, int n_in,
                              void* d_out, int out_size)
{
    const float* query = (const float*)d_in[0];
    const float* pos   = (const float*)d_in[1];
    const float* Wq  = (const float*)d_in[2];  const float* bq  = (const float*)d_in[3];
    const float* Wk  = (const float*)d_in[4];  const float* bk  = (const float*)d_in[5];
    const float* Wv  = (const float*)d_in[6];  const float* bv  = (const float*)d_in[7];
    const float* Wp1 = (const float*)d_in[8];  const float* bp1 = (const float*)d_in[9];
    const float* Wp2 = (const float*)d_in[10]; const float* bp2 = (const float*)d_in[11];
    const float* Wg  = (const float*)d_in[12]; const float* bg  = (const float*)d_in[13];
    const float* Wo  = (const float*)d_in[14]; const float* bo  = (const float*)d_in[15];
    float* out = (float*)d_out;

    cudaFuncSetAttribute(gemm_mma, cudaFuncAttributeMaxDynamicSharedMemorySize, SMEM_BYTES);
    cudaFuncSetAttribute(knn_k,   cudaFuncAttributeMaxDynamicSharedMemorySize, KNN_SMEM);

    int dev = 0, sms = 148;
    cudaGetDevice(&dev);
    cudaDeviceGetAttribute(&sms, cudaDevAttrMultiProcessorCount, dev);

    const int NT_NB = NB/128;   // 256
    const int NT_NR = NR/128;   // 2048
    const int gNB = (NT_NB < sms) ? NT_NB : sms;
    const int gNR = sms;
    const int gH  = 128;        // half-NB tile count

    // 1-5: QKV projections (Q and K split in half so knn is launch #6)
    gemm_mma<<<gH,  THREADS, SMEM_BYTES>>>(query, Wq, bq, 0, 0, 0,   128,   0);
    gemm_mma<<<gH,  THREADS, SMEM_BYTES>>>(query, Wq, bq, 0, 0, 128, 128,   0);
    gemm_mma<<<gH,  THREADS, SMEM_BYTES>>>(query, Wk, bk, 0, 0, 0,   128,   1);
    gemm_mma<<<gH,  THREADS, SMEM_BYTES>>>(query, Wk, bk, 0, 0, 128, 128,   1);
    gemm_mma<<<gNB, THREADS, SMEM_BYTES>>>(query, Wv, bv, 0, 0, 0,   NT_NB, 2);

    // 6: KNN (profiled by ncu -s 5 -c 1)
    knn_k<<<dim3(NPTS/32, BB), 256, KNN_SMEM>>>(pos);

    // h = gelu(lin1(rel))          [NR,128]
    buildh_k<<<NR*32/256, 256>>>(pos, Wp1, bp1);

    // pe = h @ Wp2 + bp2           [NR,128]
    gemm_mma<<<gNR, THREADS, SMEM_BYTES>>>(0, Wp2, bp2, 0, 0, 0, NT_NR, 4);

    // u = q - k_knn + pe           [NR,128]
    buildu_k<<<NR*32/256, 256>>>();

    // a = u @ Wg + bg              [NR,128]  (into g_h)
    gemm_mma<<<gNR, THREADS, SMEM_BYTES>>>(0, Wg, bg, 0, 0, 0, NT_NR, 5);

    // softmax over d + weighted sum over k -> g_res [B,N,D]
    finish_k<<<NB/2, 256>>>();

    // out = res@Wo + bo + query    [N,B,D]
    gemm_mma<<<gNB, THREADS, SMEM_BYTES>>>(query, Wo, bo, query, out, 0, NT_NB, 3);
}

// round 14
// speedup vs baseline: 3.7084x; 1.1957x over previous
#include <cuda_runtime.h>
#include <math.h>

#define NPTS 8192
#define BB   4
#define DD   128
#define KK   8
#define NB   (NPTS*BB)        // 32768
#define NR   (NB*KK)          // 262144

#define THREADS 512

#define WST2 136
#define AST2 68
#define CST  132

// smem word offsets
#define OFF_WHI 0             // 64*136 = 8704
#define OFF_WLO 8704
#define OFF_AHI 17408         // 128*68 = 8704
#define OFF_ALO 26112
#define OFF_CS  17408         // aliases AHI+ALO (needs 128*132 = 16896 <= 17408)
#define OFF_SB  34816         // bias[128]
#define OFF_IT  34944         // itot[128]
#define OFF_W1  35072         // w1[384]
#define OFF_B1  35456         // b1[128]
#define OFF_REL 35584         // rel[128*4]
#define SMEM_WORDS 36096
#define SMEM_BYTES (SMEM_WORDS*4)   // 144384

// ---------------- scratch ----------------
__device__ float g_qf[BB*NPTS*DD];
__device__ float g_kf[BB*NPTS*DD];
__device__ float g_vf[BB*NPTS*DD];
__device__ float g_res[BB*NPTS*DD];
__device__ int   g_idx[BB*NPTS*KK];
__device__ float g_pe[NR*DD];
__device__ float g_u [NR*DD];

// ---------------- bf16 helpers ----------------
__device__ __forceinline__ unsigned bfpack(float lo_elem, float hi_elem) {
    unsigned r;
    asm("cvt.rn.bf16x2.f32 %0, %1, %2;" : "=r"(r) : "f"(hi_elem), "f"(lo_elem));
    return r;
}
__device__ __forceinline__ void bfsplit(float x0, float x1,
                                        unsigned& hp, unsigned& lp) {
    hp = bfpack(x0, x1);
    float h0 = __uint_as_float(hp << 16);
    float h1 = __uint_as_float(hp & 0xFFFF0000u);
    lp = bfpack(x0 - h0, x1 - h1);
}
__device__ __forceinline__ void mma_bf16(float* c, const unsigned* a,
                                         unsigned b0, unsigned b1) {
    asm volatile(
        "mma.sync.aligned.m16n8k16.row.col.f32.bf16.bf16.f32 "
        "{%0,%1,%2,%3}, {%4,%5,%6,%7}, {%8,%9}, {%0,%1,%2,%3};"
        : "+f"(c[0]), "+f"(c[1]), "+f"(c[2]), "+f"(c[3])
        : "r"(a[0]), "r"(a[1]), "r"(a[2]), "r"(a[3]), "r"(b0), "r"(b1));
}

// ============================================================================
// bf16-split MMA GEMM, persistent, 512 threads. FUSED pipeline:
//  0/1/2: A=query rows, out scattered to g_qf/g_kf/g_vf [B,N,D]
//  3:     A=g_res (permuted rows), out -> d_out [N,B,D] + query residual
//  4:     A = gelu(lin1(rel)) built IN-BLOCK; epilogue writes g_pe AND
//         g_u = q - k_knn + pe
//  5:     A=g_u; epilogue: softmax over d + weighted sum over k -> g_res
// ============================================================================
__global__ __launch_bounds__(THREADS, 1) void gemm_mma(
    const float* __restrict__ Aext, const float* __restrict__ W,
    const float* __restrict__ bias, const float* __restrict__ resid,
    float* __restrict__ outext,
    const float* __restrict__ pos,
    const float* __restrict__ Wp1, const float* __restrict__ bp1,
    int ntiles, int mode)
{
    extern __shared__ unsigned smw[];
    unsigned* WhiP = smw + OFF_WHI;
    unsigned* WloP = smw + OFF_WLO;
    unsigned* AhiP = smw + OFF_AHI;
    unsigned* AloP = smw + OFF_ALO;
    float* Cs   = (float*)(smw + OFF_CS);
    float* sb   = (float*)(smw + OFF_SB);
    float* itot = (float*)(smw + OFF_IT);
    float* w1s  = (float*)(smw + OFF_W1);
    float* b1s  = (float*)(smw + OFF_B1);
    float* rels = (float*)(smw + OFF_REL);

    const int tid = threadIdx.x;

    // ---- W split + bias: once per block ----
    #pragma unroll
    for (int p = tid; p < 2048; p += THREADS) {
        int kk = p >> 5, nq = p & 31;
        const float4 L0 = *(const float4*)(W + (2*kk    )*128 + 4*nq);
        const float4 L1 = *(const float4*)(W + (2*kk + 1)*128 + 4*nq);
        uint4 h, l;
        bfsplit(L0.x, L1.x, h.x, l.x);
        bfsplit(L0.y, L1.y, h.y, l.y);
        bfsplit(L0.z, L1.z, h.z, l.z);
        bfsplit(L0.w, L1.w, h.w, l.w);
        *(uint4*)(WhiP + kk*WST2 + 4*nq) = h;
        *(uint4*)(WloP + kk*WST2 + 4*nq) = l;
    }
    if (tid < 128) sb[tid] = bias[tid];
    if (mode == 4) {
        // FULL strided loads (the R5-R7 bug was `if (tid < 384)` @256 threads)
        for (int i = tid; i < 3*DD; i += THREADS) w1s[i] = Wp1[i];
        for (int i = tid; i < DD;   i += THREADS) b1s[i] = bp1[i];
    }

    const float* Aptr = (mode == 3) ? (const float*)g_res :
                        (mode == 5) ? (const float*)g_u  : Aext;

    const int lane  = tid & 31;
    const int wid   = tid >> 5;
    const int warpM = (wid & 3) * 32;
    const int warpN = (wid >> 2) * 32;
    const int gid   = lane >> 2;
    const int tig   = lane & 3;
    const float scale = 0.08838834764831845f;   // 1/sqrt(128)

    for (int tile = blockIdx.x; tile < ntiles; tile += gridDim.x) {
        const int m0 = tile * 128;

        __syncthreads();   // prior tile's readers done before A overwrite
        if (mode == 4) {
            if (tid < 128) {
                int rg = m0 + tid;
                int g = rg >> 3;
                int b = g >> 13, n = g & (NPTS - 1);
                int id = g_idx[rg];
                const float* pb = pos + (size_t)b * NPTS * 3;
                rels[tid*4+0] = pb[n*3+0] - pb[id*3+0];
                rels[tid*4+1] = pb[n*3+1] - pb[id*3+1];
                rels[tid*4+2] = pb[n*3+2] - pb[id*3+2];
            }
            __syncthreads();
            #pragma unroll
            for (int p = tid; p < 8192; p += THREADS) {
                int m = p >> 6, dp = p & 63;
                int d0 = dp * 2, d1 = d0 + 1;
                float rx = rels[m*4+0], ry = rels[m*4+1], rz = rels[m*4+2];
                float z0 = fmaf(rz, w1s[256+d0], fmaf(ry, w1s[128+d0],
                           fmaf(rx, w1s[d0], b1s[d0])));
                float z1 = fmaf(rz, w1s[256+d1], fmaf(ry, w1s[128+d1],
                           fmaf(rx, w1s[d1], b1s[d1])));
                float h0 = 0.5f * z0 * (1.f + erff(z0 * 0.70710678118654752f));
                float h1 = 0.5f * z1 * (1.f + erff(z1 * 0.70710678118654752f));
                unsigned hp, lp;
                bfsplit(h0, h1, hp, lp);
                AhiP[m*AST2 + dp] = hp;
                AloP[m*AST2 + dp] = lp;
            }
        } else {
            #pragma unroll
            for (int i = tid; i < 4096; i += THREADS) {
                int m = i >> 5, cc = i & 31;
                int gm = m0 + m;
                int arow = (mode == 3) ? ((gm & 3) * NPTS + (gm >> 2)) : gm;
                float4 v = *(const float4*)(Aptr + (size_t)arow*DD + cc*4);
                uint2 h, l;
                bfsplit(v.x, v.y, h.x, l.x);
                bfsplit(v.z, v.w, h.y, l.y);
                *(uint2*)(AhiP + m*AST2 + 2*cc) = h;
                *(uint2*)(AloP + m*AST2 + 2*cc) = l;
            }
        }
        __syncthreads();

        // ---- MMA mainloop (verified R10 engine) ----
        float acc[2][4][4];
        #pragma unroll
        for (int mt = 0; mt < 2; mt++)
            #pragma unroll
            for (int nt = 0; nt < 4; nt++)
                #pragma unroll
                for (int q = 0; q < 4; q++) acc[mt][nt][q] = 0.f;

        #pragma unroll 1
        for (int ks = 0; ks < 8; ++ks) {
            const int kk0 = ks * 8;
            unsigned ahi[2][4], alo[2][4];
            #pragma unroll
            for (int mt = 0; mt < 2; mt++) {
                const int r0 = warpM + mt*16 + gid;
                ahi[mt][0] = AhiP[(r0    )*AST2 + kk0 + tig];
                ahi[mt][1] = AhiP[(r0 + 8)*AST2 + kk0 + tig];
                ahi[mt][2] = AhiP[(r0    )*AST2 + kk0 + tig + 4];
                ahi[mt][3] = AhiP[(r0 + 8)*AST2 + kk0 + tig + 4];
                alo[mt][0] = AloP[(r0    )*AST2 + kk0 + tig];
                alo[mt][1] = AloP[(r0 + 8)*AST2 + kk0 + tig];
                alo[mt][2] = AloP[(r0    )*AST2 + kk0 + tig + 4];
                alo[mt][3] = AloP[(r0 + 8)*AST2 + kk0 + tig + 4];
            }
            #pragma unroll
            for (int nt = 0; nt < 4; nt++) {
                const int nc = warpN + nt*8 + gid;
                unsigned bh0 = WhiP[(kk0 + tig    )*WST2 + nc];
                unsigned bh1 = WhiP[(kk0 + tig + 4)*WST2 + nc];
                unsigned bl0 = WloP[(kk0 + tig    )*WST2 + nc];
                unsigned bl1 = WloP[(kk0 + tig + 4)*WST2 + nc];
                #pragma unroll
                for (int mt = 0; mt < 2; mt++) {
                    mma_bf16(acc[mt][nt], ahi[mt], bh0, bh1);
                    mma_bf16(acc[mt][nt], alo[mt], bh0, bh1);
                    mma_bf16(acc[mt][nt], ahi[mt], bl0, bl1);
                }
            }
        }

        // ---- epilogues ----
        if (mode <= 3) {
            #pragma unroll
            for (int mt = 0; mt < 2; mt++) {
                #pragma unroll
                for (int half = 0; half < 2; half++) {
                    const int rl = warpM + mt*16 + gid + half*8;
                    const int gm = m0 + rl;
                    float* orow;
                    const float* rrow = 0;
                    if (mode == 0)      orow = g_qf + (size_t)((gm & 3)*NPTS + (gm >> 2)) * DD;
                    else if (mode == 1) orow = g_kf + (size_t)((gm & 3)*NPTS + (gm >> 2)) * DD;
                    else if (mode == 2) orow = g_vf + (size_t)((gm & 3)*NPTS + (gm >> 2)) * DD;
                    else { orow = outext + (size_t)gm * DD; rrow = resid + (size_t)gm * DD; }
                    #pragma unroll
                    for (int nt = 0; nt < 4; nt++) {
                        const int col = warpN + nt*8 + 2*tig;
                        float2 v;
                        v.x = acc[mt][nt][half*2    ] + sb[col];
                        v.y = acc[mt][nt][half*2 + 1] + sb[col + 1];
                        if (mode == 3) {
                            float2 rr = *(const float2*)(rrow + col);
                            v.x += rr.x; v.y += rr.y;
                        }
                        *(float2*)(orow + col) = v;
                    }
                }
            }
        } else if (mode == 4) {
            #pragma unroll
            for (int mt = 0; mt < 2; mt++) {
                #pragma unroll
                for (int half = 0; half < 2; half++) {
                    const int rl = warpM + mt*16 + gid + half*8;
                    const int rg = m0 + rl;
                    const int g = rg >> 3, bb = g >> 13;
                    const int id = g_idx[rg];
                    const float* qrow = g_qf + (size_t)g * DD;
                    const float* krow = g_kf + ((size_t)bb * NPTS + id) * DD;
                    float* perow = g_pe + (size_t)rg * DD;
                    float* urow  = g_u  + (size_t)rg * DD;
                    #pragma unroll
                    for (int nt = 0; nt < 4; nt++) {
                        const int col = warpN + nt*8 + 2*tig;
                        float2 pe;
                        pe.x = acc[mt][nt][half*2    ] + sb[col];
                        pe.y = acc[mt][nt][half*2 + 1] + sb[col + 1];
                        *(float2*)(perow + col) = pe;
                        float2 q = *(const float2*)(qrow + col);
                        float2 k = *(const float2*)(krow + col);
                        float2 u;
                        u.x = q.x - k.x + pe.x;
                        u.y = q.y - k.y + pe.y;
                        *(float2*)(urow + col) = u;
                    }
                }
            }
        } else {  // mode 5: stage -> softmax over d -> weighted sum over k
            __syncthreads();   // all warps done reading AhiP/AloP (Cs aliases)
            #pragma unroll
            for (int mt = 0; mt < 2; mt++) {
                #pragma unroll
                for (int half = 0; half < 2; half++) {
                    const int rl = warpM + mt*16 + gid + half*8;
                    #pragma unroll
                    for (int nt = 0; nt < 4; nt++) {
                        const int col = warpN + nt*8 + 2*tig;
                        Cs[rl*CST + col    ] = acc[mt][nt][half*2    ];
                        Cs[rl*CST + col + 1] = acc[mt][nt][half*2 + 1];
                    }
                }
            }
            __syncthreads();

            if (tid < 128) {
                const int r = tid;
                float* row = Cs + r*CST;
                float mx = -1e30f;
                for (int jj = 0; jj < 128; ++jj) {
                    int j = (jj + r*5) & 127;
                    float v = (row[j] + sb[j]) * scale;
                    mx = fmaxf(mx, v);
                }
                float sum = 0.f;
                for (int jj = 0; jj < 128; ++jj) {
                    int j = (jj + r*5) & 127;
                    float v = (row[j] + sb[j]) * scale;
                    float e = __expf(v - mx);
                    row[j] = e;
                    sum += e;
                }
                itot[r] = 1.0f / sum;
            }
            __syncthreads();

            const int p = tid >> 5;              // 16 points per tile
            const int dseg = (tid & 31) * 4;     // 32 segments of 4
            const int g = (m0 >> 3) + p;
            const int bb = g >> 13;
            float4 a4 = make_float4(0.f, 0.f, 0.f, 0.f);
            #pragma unroll
            for (int k = 0; k < 8; ++k) {
                const int r = p*8 + k;
                const int rg = m0 + r;
                const int id = g_idx[rg];
                const float it = itot[r];
                float4 v  = *(const float4*)(g_vf + ((size_t)bb*NPTS + id)*DD + dseg);
                float4 pe = *(const float4*)(g_pe + (size_t)rg*DD + dseg);
                const float* crow = Cs + r*CST + dseg;
                a4.x = fmaf(crow[0]*it, v.x + pe.x, a4.x);
                a4.y = fmaf(crow[1]*it, v.y + pe.y, a4.y);
                a4.z = fmaf(crow[2]*it, v.z + pe.z, a4.z);
                a4.w = fmaf(crow[3]*it, v.w + pe.w, a4.w);
            }
            *(float4*)(g_res + (size_t)g*DD + dseg) = a4;
        }
    }
}

// ============================================================================
// KNN — R10 verbatim (8-way split, shift trick, predicated chain; frozen)
// ============================================================================
__global__ __launch_bounds__(256, 1) void knn_k(const float* __restrict__ pos)
{
    __shared__ float4 cand[1032];
    __shared__ float  sd[256*8];
    __shared__ int    si[256*8];

    const int b = blockIdx.y;
    const int t = threadIdx.x;
    const int q = blockIdx.x * 32 + (t >> 3);
    const int s = t & 7;
    const float* pb = pos + (size_t)b * NPTS * 3;

    const float qx = pb[q*3], qy = pb[q*3+1], qz = pb[q*3+2];
    const float nx = -2.f*qx, ny = -2.f*qy, nz = -2.f*qz;

    float bd[8]; int bi[8];
    #pragma unroll
    for (int k = 0; k < 8; k++) { bd[k] = 1e30f; bi[k] = 0x7fffffff; }

    const int base = s * 129;
    for (int t0 = 0; t0 < NPTS; t0 += 1024) {
        __syncthreads();
        #pragma unroll
        for (int i = t; i < 1024; i += 256) {
            float x = pb[(t0+i)*3], y = pb[(t0+i)*3+1], z = pb[(t0+i)*3+2];
            cand[i + (i >> 7)] = make_float4(x, y, z, fmaf(z, z, fmaf(y, y, x*x)));
        }
        __syncthreads();
        #pragma unroll 8
        for (int m = 0; m < 128; ++m) {
            float4 c = cand[base + m];
            float sv = fmaf(nx, c.x, fmaf(ny, c.y, fmaf(nz, c.z, c.w)));
            if (sv < bd[7]) {
                bd[7] = sv; bi[7] = t0 + s*128 + m;
                #pragma unroll
                for (int r = 7; r > 0; --r) {
                    if (bd[r] < bd[r-1]) {
                        float td = bd[r]; bd[r] = bd[r-1]; bd[r-1] = td;
                        int   ti = bi[r]; bi[r] = bi[r-1]; bi[r-1] = ti;
                    }
                }
            }
        }
    }

    #pragma unroll
    for (int k = 0; k < 8; k++) { sd[t*8+k] = bd[k]; si[t*8+k] = bi[k]; }
    __syncthreads();

    if (s == 0) {
        int p[8] = {0,0,0,0,0,0,0,0};
        int* op = g_idx + ((size_t)b * NPTS + q) * KK;
        #pragma unroll
        for (int o = 0; o < 8; ++o) {
            float bdv = 1e38f; int biv = 0x7fffffff; int bl = 0;
            #pragma unroll
            for (int l = 0; l < 8; ++l) {
                float dv = sd[(t+l)*8 + p[l]];
                int   iv = si[(t+l)*8 + p[l]];
                if (dv < bdv || (dv == bdv && iv < biv)) { bdv = dv; biv = iv; bl = l; }
            }
            op[o] = biv;
            p[bl]++;
        }
    }
}

// ============================================================================
// host launch
// ============================================================================
extern "C" void kernel_launch(void* const* d_in, const int* in_sizes, int n_in,
                              void* d_out, int out_size)
{
    const float* query = (const float*)d_in[0];
    const float* pos   = (const float*)d_in[1];
    const float* Wq  = (const float*)d_in[2];  const float* bq  = (const float*)d_in[3];
    const float* Wk  = (const float*)d_in[4];  const float* bk  = (const float*)d_in[5];
    const float* Wv  = (const float*)d_in[6];  const float* bv  = (const float*)d_in[7];
    const float* Wp1 = (const float*)d_in[8];  const float* bp1 = (const float*)d_in[9];
    const float* Wp2 = (const float*)d_in[10]; const float* bp2 = (const float*)d_in[11];
    const float* Wg  = (const float*)d_in[12]; const float* bg  = (const float*)d_in[13];
    const float* Wo  = (const float*)d_in[14]; const float* bo  = (const float*)d_in[15];
    float* out = (float*)d_out;

    cudaFuncSetAttribute(gemm_mma, cudaFuncAttributeMaxDynamicSharedMemorySize, SMEM_BYTES);

    int dev = 0, sms = 148;
    cudaGetDevice(&dev);
    cudaDeviceGetAttribute(&sms, cudaDevAttrMultiProcessorCount, dev);

    const int NT_NB = NB/128;   // 256
    const int NT_NR = NR/128;   // 2048
    const int gNB = (NT_NB < sms) ? NT_NB : sms;
    const int gNR = sms;

    // KNN first (longest independent kernel)
    knn_k<<<dim3(NPTS/32, BB), 256>>>(pos);

    // QKV projections -> g_qf/g_kf/g_vf in [B,N,D]
    gemm_mma<<<gNB, THREADS, SMEM_BYTES>>>(query, Wq, bq, 0, 0, pos, 0, 0, NT_NB, 0);
    gemm_mma<<<gNB, THREADS, SMEM_BYTES>>>(query, Wk, bk, 0, 0, pos, 0, 0, NT_NB, 1);
    gemm_mma<<<gNB, THREADS, SMEM_BYTES>>>(query, Wv, bv, 0, 0, pos, 0, 0, NT_NB, 2);

    // pe = Wp2 @ gelu(lin1(rel)) built in-block; epilogue writes pe AND u
    gemm_mma<<<gNR, THREADS, SMEM_BYTES>>>(0, Wp2, bp2, 0, 0, pos, Wp1, bp1, NT_NR, 4);

    // a = u @ Wg + bg; epilogue: softmax over d + weighted sum -> g_res
    gemm_mma<<<gNR, THREADS, SMEM_BYTES>>>(0, Wg, bg, 0, 0, pos, 0, 0, NT_NR, 5);

    // out = res @ Wo + bo + query   [N,B,D]
    gemm_mma<<<gNB, THREADS, SMEM_BYTES>>>(query, Wo, bo, query, out, pos, 0, 0, NT_NB, 3);
}

// round 15
// speedup vs baseline: 3.8379x; 1.0349x over previous
#include <cuda_runtime.h>
#include <math.h>

#define NPTS 8192
#define BB   4
#define DD   128
#define KK   8
#define NB   (NPTS*BB)        // 32768
#define NR   (NB*KK)          // 262144

#define THREADS 512

#define WST2 136
#define AST2 68
#define CST  132

// smem word offsets
#define OFF_WHI 0             // 64*136 = 8704
#define OFF_WLO 8704
#define OFF_AHI 17408         // 128*68 = 8704
#define OFF_ALO 26112
#define OFF_CS  17408         // aliases AHI+ALO (needs 128*132 = 16896 <= 17408)
#define OFF_SB  34816         // bias[128]
#define OFF_IT  34944         // itot[128]
#define OFF_W1  35072         // w1[384]
#define OFF_B1  35456         // b1[128]
#define OFF_REL 35584         // rel[128*4]
#define OFF_RAW 36096         // raw A staging [128*128] floats
#define SMEM_WORDS 52480
#define SMEM_BYTES (SMEM_WORDS*4)   // 209920

// ---------------- scratch ----------------
__device__ float g_qf[BB*NPTS*DD];
__device__ float g_kf[BB*NPTS*DD];
__device__ float g_vf[BB*NPTS*DD];
__device__ float g_res[BB*NPTS*DD];
__device__ int   g_idx[BB*NPTS*KK];
__device__ float g_pe[NR*DD];
__device__ float g_u [NR*DD];

// ---------------- bf16 helpers ----------------
__device__ __forceinline__ unsigned bfpack(float lo_elem, float hi_elem) {
    unsigned r;
    asm("cvt.rn.bf16x2.f32 %0, %1, %2;" : "=r"(r) : "f"(hi_elem), "f"(lo_elem));
    return r;
}
__device__ __forceinline__ void bfsplit(float x0, float x1,
                                        unsigned& hp, unsigned& lp) {
    hp = bfpack(x0, x1);
    float h0 = __uint_as_float(hp << 16);
    float h1 = __uint_as_float(hp & 0xFFFF0000u);
    lp = bfpack(x0 - h0, x1 - h1);
}
__device__ __forceinline__ void mma_bf16(float* c, const unsigned* a,
                                         unsigned b0, unsigned b1) {
    asm volatile(
        "mma.sync.aligned.m16n8k16.row.col.f32.bf16.bf16.f32 "
        "{%0,%1,%2,%3}, {%4,%5,%6,%7}, {%8,%9}, {%0,%1,%2,%3};"
        : "+f"(c[0]), "+f"(c[1]), "+f"(c[2]), "+f"(c[3])
        : "r"(a[0]), "r"(a[1]), "r"(a[2]), "r"(a[3]), "r"(b0), "r"(b1));
}

// cp.async prefetch of one 128x128 A tile into raw staging
__device__ __forceinline__ void prefetch_A(const float* __restrict__ Aptr,
                                           int tile, int tid,
                                           unsigned raw_b, int mode) {
    const int m0 = tile * 128;
    #pragma unroll
    for (int i = tid; i < 4096; i += THREADS) {
        int m = i >> 5, cc = i & 31;
        int gm = m0 + m;
        int arow = (mode == 3) ? ((gm & 3) * NPTS + (gm >> 2)) : gm;
        const float* src = Aptr + (size_t)arow * DD + cc * 4;
        unsigned dst = raw_b + (unsigned)((m * 128 + cc * 4) * 4);
        asm volatile("cp.async.ca.shared.global [%0], [%1], 16;"
                     :: "r"(dst), "l"(src));
    }
    asm volatile("cp.async.commit_group;" ::: "memory");
}

// ============================================================================
// bf16-split MMA GEMM, persistent, 512 threads, cp.async-pipelined A tiles.
//  0/1/2: A=query rows, out scattered to g_qf/g_kf/g_vf [B,N,D]
//  3:     A=g_res (permuted rows), out -> d_out [N,B,D] + query residual
//  4:     A = gelu(lin1(rel)) built IN-BLOCK; epilogue writes g_pe AND g_u
//  5:     A=g_u; epilogue: parallel softmax over d + weighted sum -> g_res
// ============================================================================
__global__ __launch_bounds__(THREADS, 1) void gemm_mma(
    const float* __restrict__ Aext, const float* __restrict__ W,
    const float* __restrict__ bias, const float* __restrict__ resid,
    float* __restrict__ outext,
    const float* __restrict__ pos,
    const float* __restrict__ Wp1, const float* __restrict__ bp1,
    int ntiles, int mode)
{
    extern __shared__ unsigned smw[];
    unsigned* WhiP = smw + OFF_WHI;
    unsigned* WloP = smw + OFF_WLO;
    unsigned* AhiP = smw + OFF_AHI;
    unsigned* AloP = smw + OFF_ALO;
    float* Cs   = (float*)(smw + OFF_CS);
    float* sb   = (float*)(smw + OFF_SB);
    float* itot = (float*)(smw + OFF_IT);
    float* w1s  = (float*)(smw + OFF_W1);
    float* b1s  = (float*)(smw + OFF_B1);
    float* rels = (float*)(smw + OFF_REL);
    float* raw  = (float*)(smw + OFF_RAW);
    const unsigned raw_b = (unsigned)__cvta_generic_to_shared(raw);

    const int tid = threadIdx.x;

    const float* Aptr = (mode == 3) ? (const float*)g_res :
                        (mode == 5) ? (const float*)g_u  : Aext;

    // kick off first A prefetch (overlaps W split below)
    if (mode != 4 && blockIdx.x < ntiles)
        prefetch_A(Aptr, blockIdx.x, tid, raw_b, mode);

    // ---- W split + bias: once per block ----
    #pragma unroll
    for (int p = tid; p < 2048; p += THREADS) {
        int kk = p >> 5, nq = p & 31;
        const float4 L0 = *(const float4*)(W + (2*kk    )*128 + 4*nq);
        const float4 L1 = *(const float4*)(W + (2*kk + 1)*128 + 4*nq);
        uint4 h, l;
        bfsplit(L0.x, L1.x, h.x, l.x);
        bfsplit(L0.y, L1.y, h.y, l.y);
        bfsplit(L0.z, L1.z, h.z, l.z);
        bfsplit(L0.w, L1.w, h.w, l.w);
        *(uint4*)(WhiP + kk*WST2 + 4*nq) = h;
        *(uint4*)(WloP + kk*WST2 + 4*nq) = l;
    }
    if (tid < 128) sb[tid] = bias[tid];
    if (mode == 4) {
        for (int i = tid; i < 3*DD; i += THREADS) w1s[i] = Wp1[i];
        for (int i = tid; i < DD;   i += THREADS) b1s[i] = bp1[i];
    }

    const int lane  = tid & 31;
    const int wid   = tid >> 5;
    const int warpM = (wid & 3) * 32;
    const int warpN = (wid >> 2) * 32;
    const int gid   = lane >> 2;
    const int tig   = lane & 3;
    const float scale = 0.08838834764831845f;   // 1/sqrt(128)

    for (int tile = blockIdx.x; tile < ntiles; tile += gridDim.x) {
        const int m0 = tile * 128;

        if (mode == 4) {
            __syncthreads();   // prior tile's readers done before A overwrite
            if (tid < 128) {
                int rg = m0 + tid;
                int g = rg >> 3;
                int b = g >> 13, n = g & (NPTS - 1);
                int id = g_idx[rg];
                const float* pb = pos + (size_t)b * NPTS * 3;
                rels[tid*4+0] = pb[n*3+0] - pb[id*3+0];
                rels[tid*4+1] = pb[n*3+1] - pb[id*3+1];
                rels[tid*4+2] = pb[n*3+2] - pb[id*3+2];
            }
            __syncthreads();
            #pragma unroll
            for (int p = tid; p < 8192; p += THREADS) {
                int m = p >> 6, dp = p & 63;
                int d0 = dp * 2, d1 = d0 + 1;
                float rx = rels[m*4+0], ry = rels[m*4+1], rz = rels[m*4+2];
                float z0 = fmaf(rz, w1s[256+d0], fmaf(ry, w1s[128+d0],
                           fmaf(rx, w1s[d0], b1s[d0])));
                float z1 = fmaf(rz, w1s[256+d1], fmaf(ry, w1s[128+d1],
                           fmaf(rx, w1s[d1], b1s[d1])));
                float h0 = 0.5f * z0 * (1.f + erff(z0 * 0.70710678118654752f));
                float h1 = 0.5f * z1 * (1.f + erff(z1 * 0.70710678118654752f));
                unsigned hp, lp;
                bfsplit(h0, h1, hp, lp);
                AhiP[m*AST2 + dp] = hp;
                AloP[m*AST2 + dp] = lp;
            }
            __syncthreads();
        } else {
            asm volatile("cp.async.wait_group 0;" ::: "memory");
            __syncthreads();   // raw visible to all; prior tile readers done
            #pragma unroll
            for (int i = tid; i < 4096; i += THREADS) {
                int m = i >> 5, cc = i & 31;
                float4 v = *(const float4*)(raw + m*128 + cc*4);
                uint2 h, l;
                bfsplit(v.x, v.y, h.x, l.x);
                bfsplit(v.z, v.w, h.y, l.y);
                *(uint2*)(AhiP + m*AST2 + 2*cc) = h;
                *(uint2*)(AloP + m*AST2 + 2*cc) = l;
            }
            __syncthreads();   // Apack ready; raw consumed
            if (tile + gridDim.x < ntiles)
                prefetch_A(Aptr, tile + gridDim.x, tid, raw_b, mode);
        }

        // ---- MMA mainloop (verified engine) ----
        float acc[2][4][4];
        #pragma unroll
        for (int mt = 0; mt < 2; mt++)
            #pragma unroll
            for (int nt = 0; nt < 4; nt++)
                #pragma unroll
                for (int q = 0; q < 4; q++) acc[mt][nt][q] = 0.f;

        #pragma unroll 1
        for (int ks = 0; ks < 8; ++ks) {
            const int kk0 = ks * 8;
            unsigned ahi[2][4], alo[2][4];
            #pragma unroll
            for (int mt = 0; mt < 2; mt++) {
                const int r0 = warpM + mt*16 + gid;
                ahi[mt][0] = AhiP[(r0    )*AST2 + kk0 + tig];
                ahi[mt][1] = AhiP[(r0 + 8)*AST2 + kk0 + tig];
                ahi[mt][2] = AhiP[(r0    )*AST2 + kk0 + tig + 4];
                ahi[mt][3] = AhiP[(r0 + 8)*AST2 + kk0 + tig + 4];
                alo[mt][0] = AloP[(r0    )*AST2 + kk0 + tig];
                alo[mt][1] = AloP[(r0 + 8)*AST2 + kk0 + tig];
                alo[mt][2] = AloP[(r0    )*AST2 + kk0 + tig + 4];
                alo[mt][3] = AloP[(r0 + 8)*AST2 + kk0 + tig + 4];
            }
            #pragma unroll
            for (int nt = 0; nt < 4; nt++) {
                const int nc = warpN + nt*8 + gid;
                unsigned bh0 = WhiP[(kk0 + tig    )*WST2 + nc];
                unsigned bh1 = WhiP[(kk0 + tig + 4)*WST2 + nc];
                unsigned bl0 = WloP[(kk0 + tig    )*WST2 + nc];
                unsigned bl1 = WloP[(kk0 + tig + 4)*WST2 + nc];
                #pragma unroll
                for (int mt = 0; mt < 2; mt++) {
                    mma_bf16(acc[mt][nt], ahi[mt], bh0, bh1);
                    mma_bf16(acc[mt][nt], alo[mt], bh0, bh1);
                    mma_bf16(acc[mt][nt], ahi[mt], bl0, bl1);
                }
            }
        }

        // ---- epilogues ----
        if (mode <= 3) {
            #pragma unroll
            for (int mt = 0; mt < 2; mt++) {
                #pragma unroll
                for (int half = 0; half < 2; half++) {
                    const int rl = warpM + mt*16 + gid + half*8;
                    const int gm = m0 + rl;
                    float* orow;
                    const float* rrow = 0;
                    if (mode == 0)      orow = g_qf + (size_t)((gm & 3)*NPTS + (gm >> 2)) * DD;
                    else if (mode == 1) orow = g_kf + (size_t)((gm & 3)*NPTS + (gm >> 2)) * DD;
                    else if (mode == 2) orow = g_vf + (size_t)((gm & 3)*NPTS + (gm >> 2)) * DD;
                    else { orow = outext + (size_t)gm * DD; rrow = resid + (size_t)gm * DD; }
                    #pragma unroll
                    for (int nt = 0; nt < 4; nt++) {
                        const int col = warpN + nt*8 + 2*tig;
                        float2 v;
                        v.x = acc[mt][nt][half*2    ] + sb[col];
                        v.y = acc[mt][nt][half*2 + 1] + sb[col + 1];
                        if (mode == 3) {
                            float2 rr = *(const float2*)(rrow + col);
                            v.x += rr.x; v.y += rr.y;
                        }
                        *(float2*)(orow + col) = v;
                    }
                }
            }
        } else if (mode == 4) {
            #pragma unroll
            for (int mt = 0; mt < 2; mt++) {
                #pragma unroll
                for (int half = 0; half < 2; half++) {
                    const int rl = warpM + mt*16 + gid + half*8;
                    const int rg = m0 + rl;
                    const int g = rg >> 3, bb = g >> 13;
                    const int id = g_idx[rg];
                    const float* qrow = g_qf + (size_t)g * DD;
                    const float* krow = g_kf + ((size_t)bb * NPTS + id) * DD;
                    float* perow = g_pe + (size_t)rg * DD;
                    float* urow  = g_u  + (size_t)rg * DD;
                    #pragma unroll
                    for (int nt = 0; nt < 4; nt++) {
                        const int col = warpN + nt*8 + 2*tig;
                        float2 pe;
                        pe.x = acc[mt][nt][half*2    ] + sb[col];
                        pe.y = acc[mt][nt][half*2 + 1] + sb[col + 1];
                        *(float2*)(perow + col) = pe;
                        float2 q = *(const float2*)(qrow + col);
                        float2 k = *(const float2*)(krow + col);
                        float2 u;
                        u.x = q.x - k.x + pe.x;
                        u.y = q.y - k.y + pe.y;
                        *(float2*)(urow + col) = u;
                    }
                }
            }
        } else {  // mode 5: stage -> parallel softmax -> weighted sum
            __syncthreads();   // all warps done reading AhiP/AloP (Cs aliases)
            #pragma unroll
            for (int mt = 0; mt < 2; mt++) {
                #pragma unroll
                for (int half = 0; half < 2; half++) {
                    const int rl = warpM + mt*16 + gid + half*8;
                    #pragma unroll
                    for (int nt = 0; nt < 4; nt++) {
                        const int col = warpN + nt*8 + 2*tig;
                        Cs[rl*CST + col    ] = acc[mt][nt][half*2    ];
                        Cs[rl*CST + col + 1] = acc[mt][nt][half*2 + 1];
                    }
                }
            }
            __syncthreads();

            // parallel softmax: 4 threads per row, interleaved columns
            {
                const int r = tid >> 2, part = tid & 3;
                float* row = Cs + r*CST;
                float mx = -1e30f;
                #pragma unroll 8
                for (int jj = 0; jj < 32; ++jj) {
                    int j = 4*jj + part;
                    float v = (row[j] + sb[j]) * scale;
                    mx = fmaxf(mx, v);
                }
                mx = fmaxf(mx, __shfl_xor_sync(0xffffffffu, mx, 1));
                mx = fmaxf(mx, __shfl_xor_sync(0xffffffffu, mx, 2));
                float sum = 0.f;
                #pragma unroll 8
                for (int jj = 0; jj < 32; ++jj) {
                    int j = 4*jj + part;
                    float v = (row[j] + sb[j]) * scale;
                    float e = __expf(v - mx);
                    row[j] = e;
                    sum += e;
                }
                sum += __shfl_xor_sync(0xffffffffu, sum, 1);
                sum += __shfl_xor_sync(0xffffffffu, sum, 2);
                if (part == 0) itot[r] = 1.0f / sum;
            }
            __syncthreads();

            const int p = tid >> 5;              // 16 points per tile
            const int dseg = (tid & 31) * 4;     // 32 segments of 4
            const int g = (m0 >> 3) + p;
            const int bb = g >> 13;
            float4 a4 = make_float4(0.f, 0.f, 0.f, 0.f);
            #pragma unroll
            for (int k = 0; k < 8; ++k) {
                const int r = p*8 + k;
                const int rg = m0 + r;
                const int id = g_idx[rg];
                const float it = itot[r];
                float4 v  = *(const float4*)(g_vf + ((size_t)bb*NPTS + id)*DD + dseg);
                float4 pe = *(const float4*)(g_pe + (size_t)rg*DD + dseg);
                const float* crow = Cs + r*CST + dseg;
                a4.x = fmaf(crow[0]*it, v.x + pe.x, a4.x);
                a4.y = fmaf(crow[1]*it, v.y + pe.y, a4.y);
                a4.z = fmaf(crow[2]*it, v.z + pe.z, a4.z);
                a4.w = fmaf(crow[3]*it, v.w + pe.w, a4.w);
            }
            *(float4*)(g_res + (size_t)g*DD + dseg) = a4;
        }
    }
}

// ============================================================================
// KNN — frozen (8-way split, shift trick, predicated chain)
// ============================================================================
__global__ __launch_bounds__(256, 1) void knn_k(const float* __restrict__ pos)
{
    __shared__ float4 cand[1032];
    __shared__ float  sd[256*8];
    __shared__ int    si[256*8];

    const int b = blockIdx.y;
    const int t = threadIdx.x;
    const int q = blockIdx.x * 32 + (t >> 3);
    const int s = t & 7;
    const float* pb = pos + (size_t)b * NPTS * 3;

    const float qx = pb[q*3], qy = pb[q*3+1], qz = pb[q*3+2];
    const float nx = -2.f*qx, ny = -2.f*qy, nz = -2.f*qz;

    float bd[8]; int bi[8];
    #pragma unroll
    for (int k = 0; k < 8; k++) { bd[k] = 1e30f; bi[k] = 0x7fffffff; }

    const int base = s * 129;
    for (int t0 = 0; t0 < NPTS; t0 += 1024) {
        __syncthreads();
        #pragma unroll
        for (int i = t; i < 1024; i += 256) {
            float x = pb[(t0+i)*3], y = pb[(t0+i)*3+1], z = pb[(t0+i)*3+2];
            cand[i + (i >> 7)] = make_float4(x, y, z, fmaf(z, z, fmaf(y, y, x*x)));
        }
        __syncthreads();
        #pragma unroll 8
        for (int m = 0; m < 128; ++m) {
            float4 c = cand[base + m];
            float sv = fmaf(nx, c.x, fmaf(ny, c.y, fmaf(nz, c.z, c.w)));
            if (sv < bd[7]) {
                bd[7] = sv; bi[7] = t0 + s*128 + m;
                #pragma unroll
                for (int r = 7; r > 0; --r) {
                    if (bd[r] < bd[r-1]) {
                        float td = bd[r]; bd[r] = bd[r-1]; bd[r-1] = td;
                        int   ti = bi[r]; bi[r] = bi[r-1]; bi[r-1] = ti;
                    }
                }
            }
        }
    }

    #pragma unroll
    for (int k = 0; k < 8; k++) { sd[t*8+k] = bd[k]; si[t*8+k] = bi[k]; }
    __syncthreads();

    if (s == 0) {
        int p[8] = {0,0,0,0,0,0,0,0};
        int* op = g_idx + ((size_t)b * NPTS + q) * KK;
        #pragma unroll
        for (int o = 0; o < 8; ++o) {
            float bdv = 1e38f; int biv = 0x7fffffff; int bl = 0;
            #pragma unroll
            for (int l = 0; l < 8; ++l) {
                float dv = sd[(t+l)*8 + p[l]];
                int   iv = si[(t+l)*8 + p[l]];
                if (dv < bdv || (dv == bdv && iv < biv)) { bdv = dv; biv = iv; bl = l; }
            }
            op[o] = biv;
            p[bl]++;
        }
    }
}

// ============================================================================
// host launch
// ============================================================================
extern "C" void kernel_launch(void* const* d_in, const int* in_sizes, int n_in,
                              void* d_out, int out_size)
{
    const float* query = (const float*)d_in[0];
    const float* pos   = (const float*)d_in[1];
    const float* Wq  = (const float*)d_in[2];  const float* bq  = (const float*)d_in[3];
    const float* Wk  = (const float*)d_in[4];  const float* bk  = (const float*)d_in[5];
    const float* Wv  = (const float*)d_in[6];  const float* bv  = (const float*)d_in[7];
    const float* Wp1 = (const float*)d_in[8];  const float* bp1 = (const float*)d_in[9];
    const float* Wp2 = (const float*)d_in[10]; const float* bp2 = (const float*)d_in[11];
    const float* Wg  = (const float*)d_in[12]; const float* bg  = (const float*)d_in[13];
    const float* Wo  = (const float*)d_in[14]; const float* bo  = (const float*)d_in[15];
    float* out = (float*)d_out;

    cudaFuncSetAttribute(gemm_mma, cudaFuncAttributeMaxDynamicSharedMemorySize, SMEM_BYTES);

    int dev = 0, sms = 148;
    cudaGetDevice(&dev);
    cudaDeviceGetAttribute(&sms, cudaDevAttrMultiProcessorCount, dev);

    const int NT_NB = NB/128;   // 256
    const int NT_NR = NR/128;   // 2048
    const int gNB = (NT_NB < sms) ? NT_NB : sms;
    const int gNR = sms;

    // KNN first (longest independent kernel)
    knn_k<<<dim3(NPTS/32, BB), 256>>>(pos);

    // QKV projections -> g_qf/g_kf/g_vf in [B,N,D]
    gemm_mma<<<gNB, THREADS, SMEM_BYTES>>>(query, Wq, bq, 0, 0, pos, 0, 0, NT_NB, 0);
    gemm_mma<<<gNB, THREADS, SMEM_BYTES>>>(query, Wk, bk, 0, 0, pos, 0, 0, NT_NB, 1);
    gemm_mma<<<gNB, THREADS, SMEM_BYTES>>>(query, Wv, bv, 0, 0, pos, 0, 0, NT_NB, 2);

    // pe = Wp2 @ gelu(lin1(rel)) built in-block; epilogue writes pe AND u
    gemm_mma<<<gNR, THREADS, SMEM_BYTES>>>(0, Wp2, bp2, 0, 0, pos, Wp1, bp1, NT_NR, 4);

    // a = u @ Wg + bg; epilogue: softmax over d + weighted sum -> g_res
    gemm_mma<<<gNR, THREADS, SMEM_BYTES>>>(0, Wg, bg, 0, 0, pos, 0, 0, NT_NR, 5);

    // out = res @ Wo + bo + query   [N,B,D]
    gemm_mma<<<gNB, THREADS, SMEM_BYTES>>>(query, Wo, bo, query, out, pos, 0, 0, NT_NB, 3);
}

// round 16
// speedup vs baseline: 4.1987x; 1.0940x over previous
#include <cuda_runtime.h>
#include <math.h>

#define NPTS 8192
#define BB   4
#define DD   128
#define KK   8
#define NB   (NPTS*BB)        // 32768
#define NR   (NB*KK)          // 262144

#define THREADS 512

#define WST2 136
#define AST2 68
#define CST  132

// smem word offsets
#define OFF_WHI 0             // 64*136 = 8704
#define OFF_WLO 8704
#define OFF_AHI 17408         // 128*68 = 8704
#define OFF_ALO 26112
#define OFF_CS  17408         // aliases AHI+ALO (needs 128*132 = 16896 <= 17408)
#define OFF_SB  34816         // bias[128]
#define OFF_IT  34944         // itot[128]
#define OFF_W1  35072         // w1[384]
#define OFF_B1  35456         // b1[128]
#define OFF_REL 35584         // rel[128*4]
#define OFF_RAW 36096         // raw A/pe staging [128*128] floats
#define SMEM_WORDS 52480
#define SMEM_BYTES (SMEM_WORDS*4)   // 209920

// ---------------- scratch ----------------
__device__ float g_qf[BB*NPTS*DD];
__device__ float g_kf[BB*NPTS*DD];
__device__ float g_vf[BB*NPTS*DD];
__device__ float g_res[BB*NPTS*DD];
__device__ int   g_idx[BB*NPTS*KK];
__device__ float g_pe[NR*DD];

// ---------------- bf16 helpers ----------------
__device__ __forceinline__ unsigned bfpack(float lo_elem, float hi_elem) {
    unsigned r;
    asm("cvt.rn.bf16x2.f32 %0, %1, %2;" : "=r"(r) : "f"(hi_elem), "f"(lo_elem));
    return r;
}
__device__ __forceinline__ void bfsplit(float x0, float x1,
                                        unsigned& hp, unsigned& lp) {
    hp = bfpack(x0, x1);
    float h0 = __uint_as_float(hp << 16);
    float h1 = __uint_as_float(hp & 0xFFFF0000u);
    lp = bfpack(x0 - h0, x1 - h1);
}
__device__ __forceinline__ void mma_bf16(float* c, const unsigned* a,
                                         unsigned b0, unsigned b1) {
    asm volatile(
        "mma.sync.aligned.m16n8k16.row.col.f32.bf16.bf16.f32 "
        "{%0,%1,%2,%3}, {%4,%5,%6,%7}, {%8,%9}, {%0,%1,%2,%3};"
        : "+f"(c[0]), "+f"(c[1]), "+f"(c[2]), "+f"(c[3])
        : "r"(a[0]), "r"(a[1]), "r"(a[2]), "r"(a[3]), "r"(b0), "r"(b1));
}

// cp.async prefetch of one 128x128 fp32 tile into raw staging
__device__ __forceinline__ void prefetch_A(const float* __restrict__ Aptr,
                                           int tile, int tid,
                                           unsigned raw_b, int mode) {
    const int m0 = tile * 128;
    #pragma unroll
    for (int i = tid; i < 4096; i += THREADS) {
        int m = i >> 5, cc = i & 31;
        int gm = m0 + m;
        int arow = (mode == 3) ? ((gm & 3) * NPTS + (gm >> 2)) : gm;
        const float* src = Aptr + (size_t)arow * DD + cc * 4;
        unsigned dst = raw_b + (unsigned)((m * 128 + cc * 4) * 4);
        asm volatile("cp.async.ca.shared.global [%0], [%1], 16;"
                     :: "r"(dst), "l"(src));
    }
    asm volatile("cp.async.commit_group;" ::: "memory");
}

// ============================================================================
// bf16-split MMA GEMM, persistent, 512 threads, cp.async-pipelined.
//  0/1/2: A=query rows, out scattered to g_qf/g_kf/g_vf [B,N,D]
//  3:     A=g_res (permuted rows), out -> d_out [N,B,D] + query residual
//  4:     A = gelu(lin1(rel)) built IN-BLOCK; epilogue writes g_pe only
//  5:     pe tile staged via cp.async; A = u = q - k + pe built in pack;
//         epilogue: parallel softmax + weighted sum (pe from smem) -> g_res
// ============================================================================
__global__ __launch_bounds__(THREADS, 1) void gemm_mma(
    const float* __restrict__ Aext, const float* __restrict__ W,
    const float* __restrict__ bias, const float* __restrict__ resid,
    float* __restrict__ outext,
    const float* __restrict__ pos,
    const float* __restrict__ Wp1, const float* __restrict__ bp1,
    int ntiles, int mode)
{
    extern __shared__ unsigned smw[];
    unsigned* WhiP = smw + OFF_WHI;
    unsigned* WloP = smw + OFF_WLO;
    unsigned* AhiP = smw + OFF_AHI;
    unsigned* AloP = smw + OFF_ALO;
    float* Cs   = (float*)(smw + OFF_CS);
    float* sb   = (float*)(smw + OFF_SB);
    float* itot = (float*)(smw + OFF_IT);
    float* w1s  = (float*)(smw + OFF_W1);
    float* b1s  = (float*)(smw + OFF_B1);
    float* rels = (float*)(smw + OFF_REL);
    float* raw  = (float*)(smw + OFF_RAW);
    const unsigned raw_b = (unsigned)__cvta_generic_to_shared(raw);

    const int tid = threadIdx.x;

    const float* Aptr = (mode == 3) ? (const float*)g_res :
                        (mode == 5) ? (const float*)g_pe : Aext;

    // kick off first tile prefetch (overlaps W split below)
    if (mode != 4 && blockIdx.x < ntiles)
        prefetch_A(Aptr, blockIdx.x, tid, raw_b, mode);

    // ---- W split + bias: once per block ----
    #pragma unroll
    for (int p = tid; p < 2048; p += THREADS) {
        int kk = p >> 5, nq = p & 31;
        const float4 L0 = *(const float4*)(W + (2*kk    )*128 + 4*nq);
        const float4 L1 = *(const float4*)(W + (2*kk + 1)*128 + 4*nq);
        uint4 h, l;
        bfsplit(L0.x, L1.x, h.x, l.x);
        bfsplit(L0.y, L1.y, h.y, l.y);
        bfsplit(L0.z, L1.z, h.z, l.z);
        bfsplit(L0.w, L1.w, h.w, l.w);
        *(uint4*)(WhiP + kk*WST2 + 4*nq) = h;
        *(uint4*)(WloP + kk*WST2 + 4*nq) = l;
    }
    if (tid < 128) sb[tid] = bias[tid];
    if (mode == 4) {
        for (int i = tid; i < 3*DD; i += THREADS) w1s[i] = Wp1[i];
        for (int i = tid; i < DD;   i += THREADS) b1s[i] = bp1[i];
    }

    const int lane  = tid & 31;
    const int wid   = tid >> 5;
    const int warpM = (wid & 3) * 32;
    const int warpN = (wid >> 2) * 32;
    const int gid   = lane >> 2;
    const int tig   = lane & 3;
    const float scale = 0.08838834764831845f;   // 1/sqrt(128)

    for (int tile = blockIdx.x; tile < ntiles; tile += gridDim.x) {
        const int m0 = tile * 128;

        if (mode == 4) {
            __syncthreads();   // prior tile's readers done before A overwrite
            if (tid < 128) {
                int rg = m0 + tid;
                int g = rg >> 3;
                int b = g >> 13, n = g & (NPTS - 1);
                int id = g_idx[rg];
                const float* pb = pos + (size_t)b * NPTS * 3;
                rels[tid*4+0] = pb[n*3+0] - pb[id*3+0];
                rels[tid*4+1] = pb[n*3+1] - pb[id*3+1];
                rels[tid*4+2] = pb[n*3+2] - pb[id*3+2];
            }
            __syncthreads();
            #pragma unroll
            for (int p = tid; p < 8192; p += THREADS) {
                int m = p >> 6, dp = p & 63;
                int d0 = dp * 2, d1 = d0 + 1;
                float rx = rels[m*4+0], ry = rels[m*4+1], rz = rels[m*4+2];
                float z0 = fmaf(rz, w1s[256+d0], fmaf(ry, w1s[128+d0],
                           fmaf(rx, w1s[d0], b1s[d0])));
                float z1 = fmaf(rz, w1s[256+d1], fmaf(ry, w1s[128+d1],
                           fmaf(rx, w1s[d1], b1s[d1])));
                float h0 = 0.5f * z0 * (1.f + erff(z0 * 0.70710678118654752f));
                float h1 = 0.5f * z1 * (1.f + erff(z1 * 0.70710678118654752f));
                unsigned hp, lp;
                bfsplit(h0, h1, hp, lp);
                AhiP[m*AST2 + dp] = hp;
                AloP[m*AST2 + dp] = lp;
            }
            __syncthreads();
        } else if (mode == 5) {
            asm volatile("cp.async.wait_group 0;" ::: "memory");
            __syncthreads();   // raw (pe tile) visible; prior readers done
            // pack u = q - k + pe  (raw keeps pe for the epilogue)
            #pragma unroll
            for (int i = tid; i < 4096; i += THREADS) {
                int m = i >> 5, cc = i & 31;
                int rg = m0 + m;
                int g = rg >> 3, bb = g >> 13;
                int id = g_idx[rg];
                float4 pe = *(const float4*)(raw + m*128 + cc*4);
                float4 q = *(const float4*)(g_qf + (size_t)g*DD + cc*4);
                float4 k = *(const float4*)(g_kf + ((size_t)bb*NPTS + id)*DD + cc*4);
                float4 u;
                u.x = q.x - k.x + pe.x; u.y = q.y - k.y + pe.y;
                u.z = q.z - k.z + pe.z; u.w = q.w - k.w + pe.w;
                uint2 h, l;
                bfsplit(u.x, u.y, h.x, l.x);
                bfsplit(u.z, u.w, h.y, l.y);
                *(uint2*)(AhiP + m*AST2 + 2*cc) = h;
                *(uint2*)(AloP + m*AST2 + 2*cc) = l;
            }
            __syncthreads();
        } else {
            asm volatile("cp.async.wait_group 0;" ::: "memory");
            __syncthreads();
            #pragma unroll
            for (int i = tid; i < 4096; i += THREADS) {
                int m = i >> 5, cc = i & 31;
                float4 v = *(const float4*)(raw + m*128 + cc*4);
                uint2 h, l;
                bfsplit(v.x, v.y, h.x, l.x);
                bfsplit(v.z, v.w, h.y, l.y);
                *(uint2*)(AhiP + m*AST2 + 2*cc) = h;
                *(uint2*)(AloP + m*AST2 + 2*cc) = l;
            }
            __syncthreads();   // Apack ready; raw consumed
            if (tile + gridDim.x < ntiles)
                prefetch_A(Aptr, tile + gridDim.x, tid, raw_b, mode);
        }

        // ---- MMA mainloop (verified engine) ----
        float acc[2][4][4];
        #pragma unroll
        for (int mt = 0; mt < 2; mt++)
            #pragma unroll
            for (int nt = 0; nt < 4; nt++)
                #pragma unroll
                for (int q = 0; q < 4; q++) acc[mt][nt][q] = 0.f;

        #pragma unroll 1
        for (int ks = 0; ks < 8; ++ks) {
            const int kk0 = ks * 8;
            unsigned ahi[2][4], alo[2][4];
            #pragma unroll
            for (int mt = 0; mt < 2; mt++) {
                const int r0 = warpM + mt*16 + gid;
                ahi[mt][0] = AhiP[(r0    )*AST2 + kk0 + tig];
                ahi[mt][1] = AhiP[(r0 + 8)*AST2 + kk0 + tig];
                ahi[mt][2] = AhiP[(r0    )*AST2 + kk0 + tig + 4];
                ahi[mt][3] = AhiP[(r0 + 8)*AST2 + kk0 + tig + 4];
                alo[mt][0] = AloP[(r0    )*AST2 + kk0 + tig];
                alo[mt][1] = AloP[(r0 + 8)*AST2 + kk0 + tig];
                alo[mt][2] = AloP[(r0    )*AST2 + kk0 + tig + 4];
                alo[mt][3] = AloP[(r0 + 8)*AST2 + kk0 + tig + 4];
            }
            #pragma unroll
            for (int nt = 0; nt < 4; nt++) {
                const int nc = warpN + nt*8 + gid;
                unsigned bh0 = WhiP[(kk0 + tig    )*WST2 + nc];
                unsigned bh1 = WhiP[(kk0 + tig + 4)*WST2 + nc];
                unsigned bl0 = WloP[(kk0 + tig    )*WST2 + nc];
                unsigned bl1 = WloP[(kk0 + tig + 4)*WST2 + nc];
                #pragma unroll
                for (int mt = 0; mt < 2; mt++) {
                    mma_bf16(acc[mt][nt], ahi[mt], bh0, bh1);
                    mma_bf16(acc[mt][nt], alo[mt], bh0, bh1);
                    mma_bf16(acc[mt][nt], ahi[mt], bl0, bl1);
                }
            }
        }

        // ---- epilogues ----
        if (mode <= 3) {
            #pragma unroll
            for (int mt = 0; mt < 2; mt++) {
                #pragma unroll
                for (int half = 0; half < 2; half++) {
                    const int rl = warpM + mt*16 + gid + half*8;
                    const int gm = m0 + rl;
                    float* orow;
                    const float* rrow = 0;
                    if (mode == 0)      orow = g_qf + (size_t)((gm & 3)*NPTS + (gm >> 2)) * DD;
                    else if (mode == 1) orow = g_kf + (size_t)((gm & 3)*NPTS + (gm >> 2)) * DD;
                    else if (mode == 2) orow = g_vf + (size_t)((gm & 3)*NPTS + (gm >> 2)) * DD;
                    else { orow = outext + (size_t)gm * DD; rrow = resid + (size_t)gm * DD; }
                    #pragma unroll
                    for (int nt = 0; nt < 4; nt++) {
                        const int col = warpN + nt*8 + 2*tig;
                        float2 v;
                        v.x = acc[mt][nt][half*2    ] + sb[col];
                        v.y = acc[mt][nt][half*2 + 1] + sb[col + 1];
                        if (mode == 3) {
                            float2 rr = *(const float2*)(rrow + col);
                            v.x += rr.x; v.y += rr.y;
                        }
                        *(float2*)(orow + col) = v;
                    }
                }
            }
        } else if (mode == 4) {
            #pragma unroll
            for (int mt = 0; mt < 2; mt++) {
                #pragma unroll
                for (int half = 0; half < 2; half++) {
                    const int rl = warpM + mt*16 + gid + half*8;
                    const int rg = m0 + rl;
                    float* perow = g_pe + (size_t)rg * DD;
                    #pragma unroll
                    for (int nt = 0; nt < 4; nt++) {
                        const int col = warpN + nt*8 + 2*tig;
                        float2 pe;
                        pe.x = acc[mt][nt][half*2    ] + sb[col];
                        pe.y = acc[mt][nt][half*2 + 1] + sb[col + 1];
                        *(float2*)(perow + col) = pe;
                    }
                }
            }
        } else {  // mode 5
            __syncthreads();   // all warps done reading AhiP/AloP (Cs aliases)
            #pragma unroll
            for (int mt = 0; mt < 2; mt++) {
                #pragma unroll
                for (int half = 0; half < 2; half++) {
                    const int rl = warpM + mt*16 + gid + half*8;
                    #pragma unroll
                    for (int nt = 0; nt < 4; nt++) {
                        const int col = warpN + nt*8 + 2*tig;
                        Cs[rl*CST + col    ] = acc[mt][nt][half*2    ];
                        Cs[rl*CST + col + 1] = acc[mt][nt][half*2 + 1];
                    }
                }
            }
            __syncthreads();

            // parallel softmax: 4 threads per row
            {
                const int r = tid >> 2, part = tid & 3;
                float* row = Cs + r*CST;
                float mx = -1e30f;
                #pragma unroll 8
                for (int jj = 0; jj < 32; ++jj) {
                    int j = 4*jj + part;
                    float v = (row[j] + sb[j]) * scale;
                    mx = fmaxf(mx, v);
                }
                mx = fmaxf(mx, __shfl_xor_sync(0xffffffffu, mx, 1));
                mx = fmaxf(mx, __shfl_xor_sync(0xffffffffu, mx, 2));
                float sum = 0.f;
                #pragma unroll 8
                for (int jj = 0; jj < 32; ++jj) {
                    int j = 4*jj + part;
                    float v = (row[j] + sb[j]) * scale;
                    float e = __expf(v - mx);
                    row[j] = e;
                    sum += e;
                }
                sum += __shfl_xor_sync(0xffffffffu, sum, 1);
                sum += __shfl_xor_sync(0xffffffffu, sum, 2);
                if (part == 0) itot[r] = 1.0f / sum;
            }
            __syncthreads();

            // weighted sum: sm from Cs, pe from raw (smem), v gathered (L2)
            {
                const int p = tid >> 5;
                const int dseg = (tid & 31) * 4;
                const int g = (m0 >> 3) + p;
                const int bb = g >> 13;
                float4 a4 = make_float4(0.f, 0.f, 0.f, 0.f);
                #pragma unroll
                for (int k = 0; k < 8; ++k) {
                    const int r = p*8 + k;
                    const int rg = m0 + r;
                    const int id = g_idx[rg];
                    const float it = itot[r];
                    float4 v  = *(const float4*)(g_vf + ((size_t)bb*NPTS + id)*DD + dseg);
                    float4 pe = *(const float4*)(raw + r*128 + dseg);
                    const float* crow = Cs + r*CST + dseg;
                    a4.x = fmaf(crow[0]*it, v.x + pe.x, a4.x);
                    a4.y = fmaf(crow[1]*it, v.y + pe.y, a4.y);
                    a4.z = fmaf(crow[2]*it, v.z + pe.z, a4.z);
                    a4.w = fmaf(crow[3]*it, v.w + pe.w, a4.w);
                }
                *(float4*)(g_res + (size_t)g*DD + dseg) = a4;
            }
            __syncthreads();   // raw reads complete before next prefetch
            if (tile + gridDim.x < ntiles)
                prefetch_A(Aptr, tile + gridDim.x, tid, raw_b, mode);
        }
    }
}

// ============================================================================
// KNN — frozen (8-way split, shift trick, predicated chain)
// ============================================================================
__global__ __launch_bounds__(256, 1) void knn_k(const float* __restrict__ pos)
{
    __shared__ float4 cand[1032];
    __shared__ float  sd[256*8];
    __shared__ int    si[256*8];

    const int b = blockIdx.y;
    const int t = threadIdx.x;
    const int q = blockIdx.x * 32 + (t >> 3);
    const int s = t & 7;
    const float* pb = pos + (size_t)b * NPTS * 3;

    const float qx = pb[q*3], qy = pb[q*3+1], qz = pb[q*3+2];
    const float nx = -2.f*qx, ny = -2.f*qy, nz = -2.f*qz;

    float bd[8]; int bi[8];
    #pragma unroll
    for (int k = 0; k < 8; k++) { bd[k] = 1e30f; bi[k] = 0x7fffffff; }

    const int base = s * 129;
    for (int t0 = 0; t0 < NPTS; t0 += 1024) {
        __syncthreads();
        #pragma unroll
        for (int i = t; i < 1024; i += 256) {
            float x = pb[(t0+i)*3], y = pb[(t0+i)*3+1], z = pb[(t0+i)*3+2];
            cand[i + (i >> 7)] = make_float4(x, y, z, fmaf(z, z, fmaf(y, y, x*x)));
        }
        __syncthreads();
        #pragma unroll 8
        for (int m = 0; m < 128; ++m) {
            float4 c = cand[base + m];
            float sv = fmaf(nx, c.x, fmaf(ny, c.y, fmaf(nz, c.z, c.w)));
            if (sv < bd[7]) {
                bd[7] = sv; bi[7] = t0 + s*128 + m;
                #pragma unroll
                for (int r = 7; r > 0; --r) {
                    if (bd[r] < bd[r-1]) {
                        float td = bd[r]; bd[r] = bd[r-1]; bd[r-1] = td;
                        int   ti = bi[r]; bi[r] = bi[r-1]; bi[r-1] = ti;
                    }
                }
            }
        }
    }

    #pragma unroll
    for (int k = 0; k < 8; k++) { sd[t*8+k] = bd[k]; si[t*8+k] = bi[k]; }
    __syncthreads();

    if (s == 0) {
        int p[8] = {0,0,0,0,0,0,0,0};
        int* op = g_idx + ((size_t)b * NPTS + q) * KK;
        #pragma unroll
        for (int o = 0; o < 8; ++o) {
            float bdv = 1e38f; int biv = 0x7fffffff; int bl = 0;
            #pragma unroll
            for (int l = 0; l < 8; ++l) {
                float dv = sd[(t+l)*8 + p[l]];
                int   iv = si[(t+l)*8 + p[l]];
                if (dv < bdv || (dv == bdv && iv < biv)) { bdv = dv; biv = iv; bl = l; }
            }
            op[o] = biv;
            p[bl]++;
        }
    }
}

// ============================================================================
// host launch — knn is the 4th launch (ncu captures launch #4)
// ============================================================================
extern "C" void kernel_launch(void* const* d_in, const int* in_sizes, int n_in,
                              void* d_out, int out_size)
{
    const float* query = (const float*)d_in[0];
    const float* pos   = (const float*)d_in[1];
    const float* Wq  = (const float*)d_in[2];  const float* bq  = (const float*)d_in[3];
    const float* Wk  = (const float*)d_in[4];  const float* bk  = (const float*)d_in[5];
    const float* Wv  = (const float*)d_in[6];  const float* bv  = (const float*)d_in[7];
    const float* Wp1 = (const float*)d_in[8];  const float* bp1 = (const float*)d_in[9];
    const float* Wp2 = (const float*)d_in[10]; const float* bp2 = (const float*)d_in[11];
    const float* Wg  = (const float*)d_in[12]; const float* bg  = (const float*)d_in[13];
    const float* Wo  = (const float*)d_in[14]; const float* bo  = (const float*)d_in[15];
    float* out = (float*)d_out;

    cudaFuncSetAttribute(gemm_mma, cudaFuncAttributeMaxDynamicSharedMemorySize, SMEM_BYTES);

    int dev = 0, sms = 148;
    cudaGetDevice(&dev);
    cudaDeviceGetAttribute(&sms, cudaDevAttrMultiProcessorCount, dev);

    const int NT_NB = NB/128;   // 256
    const int NT_NR = NR/128;   // 2048
    const int gNB = (NT_NB < sms) ? NT_NB : sms;
    const int gNR = sms;

    // 1-3: QKV projections -> g_qf/g_kf/g_vf in [B,N,D]
    gemm_mma<<<gNB, THREADS, SMEM_BYTES>>>(query, Wq, bq, 0, 0, pos, 0, 0, NT_NB, 0);
    gemm_mma<<<gNB, THREADS, SMEM_BYTES>>>(query, Wk, bk, 0, 0, pos, 0, 0, NT_NB, 1);
    gemm_mma<<<gNB, THREADS, SMEM_BYTES>>>(query, Wv, bv, 0, 0, pos, 0, 0, NT_NB, 2);

    // 4: KNN (profiled)
    knn_k<<<dim3(NPTS/32, BB), 256>>>(pos);

    // 5: pe = Wp2 @ gelu(lin1(rel)), built in-block -> g_pe
    gemm_mma<<<gNR, THREADS, SMEM_BYTES>>>(0, Wp2, bp2, 0, 0, pos, Wp1, bp1, NT_NR, 4);

    // 6: a = (q-k+pe) @ Wg + bg; softmax + weighted sum -> g_res
    gemm_mma<<<gNR, THREADS, SMEM_BYTES>>>(0, Wg, bg, 0, 0, pos, 0, 0, NT_NR, 5);

    // 7: out = res @ Wo + bo + query   [N,B,D]
    gemm_mma<<<gNB, THREADS, SMEM_BYTES>>>(query, Wo, bo, query, out, pos, 0, 0, NT_NB, 3);
}

// round 17
// speedup vs baseline: 4.5362x; 1.0804x over previous
#include <cuda_runtime.h>
#include <math.h>

#define NPTS 8192
#define BB   4
#define DD   128
#define KK   8
#define NB   (NPTS*BB)        // 32768
#define NR   (NB*KK)          // 262144

#define THREADS 512

#define WST2 136
#define AST2 68
#define CST  132

// smem word offsets
#define OFF_WHI 0             // 64*136 = 8704
#define OFF_WLO 8704
#define OFF_AHI 17408         // 128*68 = 8704
#define OFF_ALO 26112
#define OFF_CS  17408         // aliases AHI+ALO (needs 128*132 = 16896 <= 17408)
#define OFF_SB  34816         // bias[128]
#define OFF_IT  34944         // itot[128]
#define OFF_W1  35072         // w1[384]
#define OFF_B1  35456         // b1[128]
#define OFF_REL 35584         // rel[128*4]
#define OFF_RAW 36096         // raw A/pe staging [128*128] floats
#define SMEM_WORDS 52480
#define SMEM_BYTES (SMEM_WORDS*4)   // 209920

// ---------------- scratch ----------------
__device__ float g_qf[BB*NPTS*DD];
__device__ float g_kf[BB*NPTS*DD];
__device__ float g_vf[BB*NPTS*DD];
__device__ float g_res[BB*NPTS*DD];
__device__ int   g_idx[BB*NPTS*KK];
__device__ float g_pe[NR*DD];

// ---------------- bf16 helpers ----------------
__device__ __forceinline__ unsigned bfpack(float lo_elem, float hi_elem) {
    unsigned r;
    asm("cvt.rn.bf16x2.f32 %0, %1, %2;" : "=r"(r) : "f"(hi_elem), "f"(lo_elem));
    return r;
}
__device__ __forceinline__ void bfsplit(float x0, float x1,
                                        unsigned& hp, unsigned& lp) {
    hp = bfpack(x0, x1);
    float h0 = __uint_as_float(hp << 16);
    float h1 = __uint_as_float(hp & 0xFFFF0000u);
    lp = bfpack(x0 - h0, x1 - h1);
}
__device__ __forceinline__ void mma_bf16(float* c, const unsigned* a,
                                         unsigned b0, unsigned b1) {
    asm volatile(
        "mma.sync.aligned.m16n8k16.row.col.f32.bf16.bf16.f32 "
        "{%0,%1,%2,%3}, {%4,%5,%6,%7}, {%8,%9}, {%0,%1,%2,%3};"
        : "+f"(c[0]), "+f"(c[1]), "+f"(c[2]), "+f"(c[3])
        : "r"(a[0]), "r"(a[1]), "r"(a[2]), "r"(a[3]), "r"(b0), "r"(b1));
}

// cp.async prefetch of one 128x128 fp32 tile into raw staging
__device__ __forceinline__ void prefetch_A(const float* __restrict__ Aptr,
                                           int tile, int tid,
                                           unsigned raw_b, int mode) {
    const int m0 = tile * 128;
    #pragma unroll
    for (int i = tid; i < 4096; i += THREADS) {
        int m = i >> 5, cc = i & 31;
        int gm = m0 + m;
        int arow = (mode == 3) ? ((gm & 3) * NPTS + (gm >> 2)) : gm;
        const float* src = Aptr + (size_t)arow * DD + cc * 4;
        unsigned dst = raw_b + (unsigned)((m * 128 + cc * 4) * 4);
        asm volatile("cp.async.ca.shared.global [%0], [%1], 16;"
                     :: "r"(dst), "l"(src));
    }
    asm volatile("cp.async.commit_group;" ::: "memory");
}

// ============================================================================
// bf16-split MMA GEMM, persistent, 512 threads, cp.async-pipelined.
// (R16 verbatim — verified)
// ============================================================================
__global__ __launch_bounds__(THREADS, 1) void gemm_mma(
    const float* __restrict__ Aext, const float* __restrict__ W,
    const float* __restrict__ bias, const float* __restrict__ resid,
    float* __restrict__ outext,
    const float* __restrict__ pos,
    const float* __restrict__ Wp1, const float* __restrict__ bp1,
    int ntiles, int mode)
{
    extern __shared__ unsigned smw[];
    unsigned* WhiP = smw + OFF_WHI;
    unsigned* WloP = smw + OFF_WLO;
    unsigned* AhiP = smw + OFF_AHI;
    unsigned* AloP = smw + OFF_ALO;
    float* Cs   = (float*)(smw + OFF_CS);
    float* sb   = (float*)(smw + OFF_SB);
    float* itot = (float*)(smw + OFF_IT);
    float* w1s  = (float*)(smw + OFF_W1);
    float* b1s  = (float*)(smw + OFF_B1);
    float* rels = (float*)(smw + OFF_REL);
    float* raw  = (float*)(smw + OFF_RAW);
    const unsigned raw_b = (unsigned)__cvta_generic_to_shared(raw);

    const int tid = threadIdx.x;

    const float* Aptr = (mode == 3) ? (const float*)g_res :
                        (mode == 5) ? (const float*)g_pe : Aext;

    if (mode != 4 && blockIdx.x < ntiles)
        prefetch_A(Aptr, blockIdx.x, tid, raw_b, mode);

    #pragma unroll
    for (int p = tid; p < 2048; p += THREADS) {
        int kk = p >> 5, nq = p & 31;
        const float4 L0 = *(const float4*)(W + (2*kk    )*128 + 4*nq);
        const float4 L1 = *(const float4*)(W + (2*kk + 1)*128 + 4*nq);
        uint4 h, l;
        bfsplit(L0.x, L1.x, h.x, l.x);
        bfsplit(L0.y, L1.y, h.y, l.y);
        bfsplit(L0.z, L1.z, h.z, l.z);
        bfsplit(L0.w, L1.w, h.w, l.w);
        *(uint4*)(WhiP + kk*WST2 + 4*nq) = h;
        *(uint4*)(WloP + kk*WST2 + 4*nq) = l;
    }
    if (tid < 128) sb[tid] = bias[tid];
    if (mode == 4) {
        for (int i = tid; i < 3*DD; i += THREADS) w1s[i] = Wp1[i];
        for (int i = tid; i < DD;   i += THREADS) b1s[i] = bp1[i];
    }

    const int lane  = tid & 31;
    const int wid   = tid >> 5;
    const int warpM = (wid & 3) * 32;
    const int warpN = (wid >> 2) * 32;
    const int gid   = lane >> 2;
    const int tig   = lane & 3;
    const float scale = 0.08838834764831845f;   // 1/sqrt(128)

    for (int tile = blockIdx.x; tile < ntiles; tile += gridDim.x) {
        const int m0 = tile * 128;

        if (mode == 4) {
            __syncthreads();
            if (tid < 128) {
                int rg = m0 + tid;
                int g = rg >> 3;
                int b = g >> 13, n = g & (NPTS - 1);
                int id = g_idx[rg];
                const float* pb = pos + (size_t)b * NPTS * 3;
                rels[tid*4+0] = pb[n*3+0] - pb[id*3+0];
                rels[tid*4+1] = pb[n*3+1] - pb[id*3+1];
                rels[tid*4+2] = pb[n*3+2] - pb[id*3+2];
            }
            __syncthreads();
            #pragma unroll
            for (int p = tid; p < 8192; p += THREADS) {
                int m = p >> 6, dp = p & 63;
                int d0 = dp * 2, d1 = d0 + 1;
                float rx = rels[m*4+0], ry = rels[m*4+1], rz = rels[m*4+2];
                float z0 = fmaf(rz, w1s[256+d0], fmaf(ry, w1s[128+d0],
                           fmaf(rx, w1s[d0], b1s[d0])));
                float z1 = fmaf(rz, w1s[256+d1], fmaf(ry, w1s[128+d1],
                           fmaf(rx, w1s[d1], b1s[d1])));
                float h0 = 0.5f * z0 * (1.f + erff(z0 * 0.70710678118654752f));
                float h1 = 0.5f * z1 * (1.f + erff(z1 * 0.70710678118654752f));
                unsigned hp, lp;
                bfsplit(h0, h1, hp, lp);
                AhiP[m*AST2 + dp] = hp;
                AloP[m*AST2 + dp] = lp;
            }
            __syncthreads();
        } else if (mode == 5) {
            asm volatile("cp.async.wait_group 0;" ::: "memory");
            __syncthreads();
            #pragma unroll
            for (int i = tid; i < 4096; i += THREADS) {
                int m = i >> 5, cc = i & 31;
                int rg = m0 + m;
                int g = rg >> 3, bb = g >> 13;
                int id = g_idx[rg];
                float4 pe = *(const float4*)(raw + m*128 + cc*4);
                float4 q = *(const float4*)(g_qf + (size_t)g*DD + cc*4);
                float4 k = *(const float4*)(g_kf + ((size_t)bb*NPTS + id)*DD + cc*4);
                float4 u;
                u.x = q.x - k.x + pe.x; u.y = q.y - k.y + pe.y;
                u.z = q.z - k.z + pe.z; u.w = q.w - k.w + pe.w;
                uint2 h, l;
                bfsplit(u.x, u.y, h.x, l.x);
                bfsplit(u.z, u.w, h.y, l.y);
                *(uint2*)(AhiP + m*AST2 + 2*cc) = h;
                *(uint2*)(AloP + m*AST2 + 2*cc) = l;
            }
            __syncthreads();
        } else {
            asm volatile("cp.async.wait_group 0;" ::: "memory");
            __syncthreads();
            #pragma unroll
            for (int i = tid; i < 4096; i += THREADS) {
                int m = i >> 5, cc = i & 31;
                float4 v = *(const float4*)(raw + m*128 + cc*4);
                uint2 h, l;
                bfsplit(v.x, v.y, h.x, l.x);
                bfsplit(v.z, v.w, h.y, l.y);
                *(uint2*)(AhiP + m*AST2 + 2*cc) = h;
                *(uint2*)(AloP + m*AST2 + 2*cc) = l;
            }
            __syncthreads();
            if (tile + gridDim.x < ntiles)
                prefetch_A(Aptr, tile + gridDim.x, tid, raw_b, mode);
        }

        float acc[2][4][4];
        #pragma unroll
        for (int mt = 0; mt < 2; mt++)
            #pragma unroll
            for (int nt = 0; nt < 4; nt++)
                #pragma unroll
                for (int q = 0; q < 4; q++) acc[mt][nt][q] = 0.f;

        #pragma unroll 1
        for (int ks = 0; ks < 8; ++ks) {
            const int kk0 = ks * 8;
            unsigned ahi[2][4], alo[2][4];
            #pragma unroll
            for (int mt = 0; mt < 2; mt++) {
                const int r0 = warpM + mt*16 + gid;
                ahi[mt][0] = AhiP[(r0    )*AST2 + kk0 + tig];
                ahi[mt][1] = AhiP[(r0 + 8)*AST2 + kk0 + tig];
                ahi[mt][2] = AhiP[(r0    )*AST2 + kk0 + tig + 4];
                ahi[mt][3] = AhiP[(r0 + 8)*AST2 + kk0 + tig + 4];
                alo[mt][0] = AloP[(r0    )*AST2 + kk0 + tig];
                alo[mt][1] = AloP[(r0 + 8)*AST2 + kk0 + tig];
                alo[mt][2] = AloP[(r0    )*AST2 + kk0 + tig + 4];
                alo[mt][3] = AloP[(r0 + 8)*AST2 + kk0 + tig + 4];
            }
            #pragma unroll
            for (int nt = 0; nt < 4; nt++) {
                const int nc = warpN + nt*8 + gid;
                unsigned bh0 = WhiP[(kk0 + tig    )*WST2 + nc];
                unsigned bh1 = WhiP[(kk0 + tig + 4)*WST2 + nc];
                unsigned bl0 = WloP[(kk0 + tig    )*WST2 + nc];
                unsigned bl1 = WloP[(kk0 + tig + 4)*WST2 + nc];
                #pragma unroll
                for (int mt = 0; mt < 2; mt++) {
                    mma_bf16(acc[mt][nt], ahi[mt], bh0, bh1);
                    mma_bf16(acc[mt][nt], alo[mt], bh0, bh1);
                    mma_bf16(acc[mt][nt], ahi[mt], bl0, bl1);
                }
            }
        }

        if (mode <= 3) {
            #pragma unroll
            for (int mt = 0; mt < 2; mt++) {
                #pragma unroll
                for (int half = 0; half < 2; half++) {
                    const int rl = warpM + mt*16 + gid + half*8;
                    const int gm = m0 + rl;
                    float* orow;
                    const float* rrow = 0;
                    if (mode == 0)      orow = g_qf + (size_t)((gm & 3)*NPTS + (gm >> 2)) * DD;
                    else if (mode == 1) orow = g_kf + (size_t)((gm & 3)*NPTS + (gm >> 2)) * DD;
                    else if (mode == 2) orow = g_vf + (size_t)((gm & 3)*NPTS + (gm >> 2)) * DD;
                    else { orow = outext + (size_t)gm * DD; rrow = resid + (size_t)gm * DD; }
                    #pragma unroll
                    for (int nt = 0; nt < 4; nt++) {
                        const int col = warpN + nt*8 + 2*tig;
                        float2 v;
                        v.x = acc[mt][nt][half*2    ] + sb[col];
                        v.y = acc[mt][nt][half*2 + 1] + sb[col + 1];
                        if (mode == 3) {
                            float2 rr = *(const float2*)(rrow + col);
                            v.x += rr.x; v.y += rr.y;
                        }
                        *(float2*)(orow + col) = v;
                    }
                }
            }
        } else if (mode == 4) {
            #pragma unroll
            for (int mt = 0; mt < 2; mt++) {
                #pragma unroll
                for (int half = 0; half < 2; half++) {
                    const int rl = warpM + mt*16 + gid + half*8;
                    const int rg = m0 + rl;
                    float* perow = g_pe + (size_t)rg * DD;
                    #pragma unroll
                    for (int nt = 0; nt < 4; nt++) {
                        const int col = warpN + nt*8 + 2*tig;
                        float2 pe;
                        pe.x = acc[mt][nt][half*2    ] + sb[col];
                        pe.y = acc[mt][nt][half*2 + 1] + sb[col + 1];
                        *(float2*)(perow + col) = pe;
                    }
                }
            }
        } else {  // mode 5
            __syncthreads();
            #pragma unroll
            for (int mt = 0; mt < 2; mt++) {
                #pragma unroll
                for (int half = 0; half < 2; half++) {
                    const int rl = warpM + mt*16 + gid + half*8;
                    #pragma unroll
                    for (int nt = 0; nt < 4; nt++) {
                        const int col = warpN + nt*8 + 2*tig;
                        Cs[rl*CST + col    ] = acc[mt][nt][half*2    ];
                        Cs[rl*CST + col + 1] = acc[mt][nt][half*2 + 1];
                    }
                }
            }
            __syncthreads();

            {
                const int r = tid >> 2, part = tid & 3;
                float* row = Cs + r*CST;
                float mx = -1e30f;
                #pragma unroll 8
                for (int jj = 0; jj < 32; ++jj) {
                    int j = 4*jj + part;
                    float v = (row[j] + sb[j]) * scale;
                    mx = fmaxf(mx, v);
                }
                mx = fmaxf(mx, __shfl_xor_sync(0xffffffffu, mx, 1));
                mx = fmaxf(mx, __shfl_xor_sync(0xffffffffu, mx, 2));
                float sum = 0.f;
                #pragma unroll 8
                for (int jj = 0; jj < 32; ++jj) {
                    int j = 4*jj + part;
                    float v = (row[j] + sb[j]) * scale;
                    float e = __expf(v - mx);
                    row[j] = e;
                    sum += e;
                }
                sum += __shfl_xor_sync(0xffffffffu, sum, 1);
                sum += __shfl_xor_sync(0xffffffffu, sum, 2);
                if (part == 0) itot[r] = 1.0f / sum;
            }
            __syncthreads();

            {
                const int p = tid >> 5;
                const int dseg = (tid & 31) * 4;
                const int g = (m0 >> 3) + p;
                const int bb = g >> 13;
                float4 a4 = make_float4(0.f, 0.f, 0.f, 0.f);
                #pragma unroll
                for (int k = 0; k < 8; ++k) {
                    const int r = p*8 + k;
                    const int rg = m0 + r;
                    const int id = g_idx[rg];
                    const float it = itot[r];
                    float4 v  = *(const float4*)(g_vf + ((size_t)bb*NPTS + id)*DD + dseg);
                    float4 pe = *(const float4*)(raw + r*128 + dseg);
                    const float* crow = Cs + r*CST + dseg;
                    a4.x = fmaf(crow[0]*it, v.x + pe.x, a4.x);
                    a4.y = fmaf(crow[1]*it, v.y + pe.y, a4.y);
                    a4.z = fmaf(crow[2]*it, v.z + pe.z, a4.z);
                    a4.w = fmaf(crow[3]*it, v.w + pe.w, a4.w);
                }
                *(float4*)(g_res + (size_t)g*DD + dseg) = a4;
            }
            __syncthreads();
            if (tile + gridDim.x < ntiles)
                prefetch_A(Aptr, tile + gridDim.x, tid, raw_b, mode);
        }
    }
}

// ============================================================================
// KNN v7: 8-way split + shift trick + WARP-SHARED THRESHOLD.
// The 8 splits of a query are lanes (q*8..q*8+7) of one warp; every 32
// candidates the 8 lanes min-reduce bd[7] via shfl.xor -> shared threshold
// st >= global-d8 at all times (8th-best of a subset >= 8th-best of set),
// so gating inserts on sv < min(bd7, st) prunes only non-top-8 candidates.
// The insert chain sits behind a warp-uniform __any_sync branch so it
// really is skipped when no lane inserts (~86% of iterations after warmup).
// ============================================================================
__global__ __launch_bounds__(256, 4) void knn_k(const float* __restrict__ pos)
{
    __shared__ float4 cand[1032];
    __shared__ float  sd[256*8];
    __shared__ int    si[256*8];

    const int b = blockIdx.y;
    const int t = threadIdx.x;
    const int q = blockIdx.x * 32 + (t >> 3);
    const int s = t & 7;
    const float* pb = pos + (size_t)b * NPTS * 3;

    const float qx = pb[q*3], qy = pb[q*3+1], qz = pb[q*3+2];
    const float nx = -2.f*qx, ny = -2.f*qy, nz = -2.f*qz;

    float bd[8]; int bi[8];
    #pragma unroll
    for (int k = 0; k < 8; k++) { bd[k] = 1e30f; bi[k] = 0x7fffffff; }
    float gate = 1e30f;   // min(st, bd[7])

    const int base = s * 129;
    for (int t0 = 0; t0 < NPTS; t0 += 1024) {
        __syncthreads();
        #pragma unroll
        for (int i = t; i < 1024; i += 256) {
            float x = pb[(t0+i)*3], y = pb[(t0+i)*3+1], z = pb[(t0+i)*3+2];
            cand[i + (i >> 7)] = make_float4(x, y, z, fmaf(z, z, fmaf(y, y, x*x)));
        }
        __syncthreads();
        #pragma unroll 1
        for (int blk = 0; blk < 4; ++blk) {
            const int mb = blk * 32;
            #pragma unroll
            for (int mm = 0; mm < 32; ++mm) {
                float4 c = cand[base + mb + mm];
                float sv = fmaf(nx, c.x, fmaf(ny, c.y, fmaf(nz, c.z, c.w)));
                if (__any_sync(0xffffffffu, sv < gate)) {
                    if (sv < gate) {
                        bd[7] = sv; bi[7] = t0 + s*128 + mb + mm;
                        #pragma unroll
                        for (int r = 7; r > 0; --r) {
                            if (bd[r] < bd[r-1]) {
                                float td = bd[r]; bd[r] = bd[r-1]; bd[r-1] = td;
                                int   ti = bi[r]; bi[r] = bi[r-1]; bi[r-1] = ti;
                            }
                        }
                        gate = fminf(gate, bd[7]);
                    }
                }
            }
            // share threshold across the 8 splits of this query (same warp)
            float st = bd[7];
            st = fminf(st, __shfl_xor_sync(0xffffffffu, st, 1));
            st = fminf(st, __shfl_xor_sync(0xffffffffu, st, 2));
            st = fminf(st, __shfl_xor_sync(0xffffffffu, st, 4));
            gate = fminf(st, bd[7]);
        }
    }

    #pragma unroll
    for (int k = 0; k < 8; k++) { sd[t*8+k] = bd[k]; si[t*8+k] = bi[k]; }
    __syncthreads();

    if (s == 0) {
        int p[8] = {0,0,0,0,0,0,0,0};
        int* op = g_idx + ((size_t)b * NPTS + q) * KK;
        #pragma unroll
        for (int o = 0; o < 8; ++o) {
            float bdv = 1e38f; int biv = 0x7fffffff; int bl = 0;
            #pragma unroll
            for (int l = 0; l < 8; ++l) {
                float dv = sd[(t+l)*8 + p[l]];
                int   iv = si[(t+l)*8 + p[l]];
                if (dv < bdv || (dv == bdv && iv < biv)) { bdv = dv; biv = iv; bl = l; }
            }
            op[o] = biv;
            p[bl]++;
        }
    }
}

// ============================================================================
// host launch — knn is the 4th launch (ncu captures launch #4)
// ============================================================================
extern "C" void kernel_launch(void* const* d_in, const int* in_sizes, int n_in,
                              void* d_out, int out_size)
{
    const float* query = (const float*)d_in[0];
    const float* pos   = (const float*)d_in[1];
    const float* Wq  = (const float*)d_in[2];  const float* bq  = (const float*)d_in[3];
    const float* Wk  = (const float*)d_in[4];  const float* bk  = (const float*)d_in[5];
    const float* Wv  = (const float*)d_in[6];  const float* bv  = (const float*)d_in[7];
    const float* Wp1 = (const float*)d_in[8];  const float* bp1 = (const float*)d_in[9];
    const float* Wp2 = (const float*)d_in[10]; const float* bp2 = (const float*)d_in[11];
    const float* Wg  = (const float*)d_in[12]; const float* bg  = (const float*)d_in[13];
    const float* Wo  = (const float*)d_in[14]; const float* bo  = (const float*)d_in[15];
    float* out = (float*)d_out;

    cudaFuncSetAttribute(gemm_mma, cudaFuncAttributeMaxDynamicSharedMemorySize, SMEM_BYTES);

    int dev = 0, sms = 148;
    cudaGetDevice(&dev);
    cudaDeviceGetAttribute(&sms, cudaDevAttrMultiProcessorCount, dev);

    const int NT_NB = NB/128;   // 256
    const int NT_NR = NR/128;   // 2048
    const int gNB = (NT_NB < sms) ? NT_NB : sms;
    const int gNR = sms;

    // 1-3: QKV projections -> g_qf/g_kf/g_vf in [B,N,D]
    gemm_mma<<<gNB, THREADS, SMEM_BYTES>>>(query, Wq, bq, 0, 0, pos, 0, 0, NT_NB, 0);
    gemm_mma<<<gNB, THREADS, SMEM_BYTES>>>(query, Wk, bk, 0, 0, pos, 0, 0, NT_NB, 1);
    gemm_mma<<<gNB, THREADS, SMEM_BYTES>>>(query, Wv, bv, 0, 0, pos, 0, 0, NT_NB, 2);

    // 4: KNN (profiled)
    knn_k<<<dim3(NPTS/32, BB), 256>>>(pos);

    // 5: pe = Wp2 @ gelu(lin1(rel)), built in-block -> g_pe
    gemm_mma<<<gNR, THREADS, SMEM_BYTES>>>(0, Wp2, bp2, 0, 0, pos, Wp1, bp1, NT_NR, 4);

    // 6: a = (q-k+pe) @ Wg + bg; softmax + weighted sum -> g_res
    gemm_mma<<<gNR, THREADS, SMEM_BYTES>>>(0, Wg, bg, 0, 0, pos, 0, 0, NT_NR, 5);

    // 7: out = res @ Wo + bo + query   [N,B,D]
    gemm_mma<<<gNB, THREADS, SMEM_BYTES>>>(query, Wo, bo, query, out, pos, 0, 0, NT_NB, 3);
}